// round 3
// baseline (speedup 1.0000x reference)
#include <cuda_runtime.h>
#include <cuda_bf16.h>
#include <math.h>

// Problem constants (fixed shapes)
#define NN   50000
#define EE   800000
#define FIN  128
#define HEADS 8
#define HID  32
#define OUTC 4
#define HC1  (HEADS*HID)   // 256
#define HC2  (HEADS*OUTC)  // 32
#define NEG  0.2f

// ---------------- scratch (__device__ globals; no runtime allocation) -------
__device__ float g_h1[NN * HC1];        // x @ W1
__device__ float g_o1[NN * HC1];        // layer-1 output (bias + lrelu applied)
__device__ float g_h2[NN * HC2];        // o1 @ W2
__device__ float g_asrc1[NN * HEADS], g_adst1[NN * HEADS];
__device__ float g_asrc2[NN * HEADS], g_adst2[NN * HEADS];
__device__ int   g_rowptr[NN + 1];
__device__ int   g_counts[NN];          // histogram, then scatter cursor
__device__ int   g_csrsrc[EE + NN];

// ---------------- SGEMM: C[M,N] = A[M,K] @ B[K,N], row-major ----------------
template<int BM, int BN, int BK, int TM, int TN>
__global__ void sgemm_kernel(int M, int N, int K,
                             const float* __restrict__ A,
                             const float* __restrict__ B,
                             float* __restrict__ C) {
    constexpr int THREADS = (BM / TM) * (BN / TN);
    constexpr int KV = BK / 4;
    constexpr int NV = BN / 4;
    __shared__ float As[BK][BM + 4];
    __shared__ float Bs[BK][BN + 4];

    const int tid = threadIdx.x;
    const int blockRow = blockIdx.y * BM;
    const int blockCol = blockIdx.x * BN;
    const int tCol = (tid % (BN / TN)) * TN;
    const int tRow = (tid / (BN / TN)) * TM;

    float acc[TM][TN];
#pragma unroll
    for (int i = 0; i < TM; i++)
#pragma unroll
        for (int j = 0; j < TN; j++) acc[i][j] = 0.f;

    for (int k0 = 0; k0 < K; k0 += BK) {
#pragma unroll
        for (int i = tid; i < BM * KV; i += THREADS) {
            int m = i / KV, k4 = i % KV;
            int gm = blockRow + m;
            float4 v = make_float4(0.f, 0.f, 0.f, 0.f);
            if (gm < M) v = *(const float4*)&A[(size_t)gm * K + k0 + k4 * 4];
            As[k4 * 4 + 0][m] = v.x;
            As[k4 * 4 + 1][m] = v.y;
            As[k4 * 4 + 2][m] = v.z;
            As[k4 * 4 + 3][m] = v.w;
        }
#pragma unroll
        for (int i = tid; i < BK * NV; i += THREADS) {
            int k = i / NV, n4 = i % NV;
            *(float4*)&Bs[k][n4 * 4] =
                *(const float4*)&B[(size_t)(k0 + k) * N + blockCol + n4 * 4];
        }
        __syncthreads();

#pragma unroll
        for (int kk = 0; kk < BK; kk++) {
            float ra[TM], rb[TN];
#pragma unroll
            for (int im = 0; im < TM / 4; im++) {
                float4 a4 = *(const float4*)&As[kk][tRow + im * 4];
                ra[im * 4 + 0] = a4.x; ra[im * 4 + 1] = a4.y;
                ra[im * 4 + 2] = a4.z; ra[im * 4 + 3] = a4.w;
            }
#pragma unroll
            for (int jn = 0; jn < TN / 4; jn++) {
                float4 b4 = *(const float4*)&Bs[kk][tCol + jn * 4];
                rb[jn * 4 + 0] = b4.x; rb[jn * 4 + 1] = b4.y;
                rb[jn * 4 + 2] = b4.z; rb[jn * 4 + 3] = b4.w;
            }
#pragma unroll
            for (int i = 0; i < TM; i++)
#pragma unroll
                for (int j = 0; j < TN; j++)
                    acc[i][j] = fmaf(ra[i], rb[j], acc[i][j]);
        }
        __syncthreads();
    }

#pragma unroll
    for (int i = 0; i < TM; i++) {
        int gm = blockRow + tRow + i;
        if (gm < M) {
#pragma unroll
            for (int j4 = 0; j4 < TN / 4; j4++) {
                float4 v = make_float4(acc[i][j4 * 4 + 0], acc[i][j4 * 4 + 1],
                                       acc[i][j4 * 4 + 2], acc[i][j4 * 4 + 3]);
                *(float4*)&C[(size_t)gm * N + blockCol + tCol + j4 * 4] = v;
            }
        }
    }
}

// ---------------- alpha dot products: asrc[n,h], adst[n,h] ------------------
template<int C>
__global__ void alphas_kernel(const float* __restrict__ h,
                              const float* __restrict__ a_src,
                              const float* __restrict__ a_dst,
                              float* __restrict__ asrc,
                              float* __restrict__ adst) {
    int i = blockIdx.x * blockDim.x + threadIdx.x;   // i = n*HEADS + head
    if (i >= NN * HEADS) return;
    int hh = i & (HEADS - 1);
    const float4* hp = (const float4*)(h + (size_t)(i >> 3) * (HEADS * C) + hh * C);
    const float4* s4 = (const float4*)(a_src + hh * C);
    const float4* d4 = (const float4*)(a_dst + hh * C);
    float s1 = 0.f, s2 = 0.f;
#pragma unroll
    for (int c = 0; c < C / 4; c++) {
        float4 v = hp[c];
        float4 a = s4[c];
        float4 b = d4[c];
        s1 = fmaf(v.x, a.x, fmaf(v.y, a.y, fmaf(v.z, a.z, fmaf(v.w, a.w, s1))));
        s2 = fmaf(v.x, b.x, fmaf(v.y, b.y, fmaf(v.z, b.z, fmaf(v.w, b.w, s2))));
    }
    asrc[i] = s1;
    adst[i] = s2;
}

// ---------------- CSR construction ------------------------------------------
__global__ void count_kernel(const int* __restrict__ dst) {
    int e = blockIdx.x * blockDim.x + threadIdx.x;
    if (e < EE) atomicAdd(&g_counts[dst[e]], 1);
}

// Fused: scan of (counts+1) -> rowptr, self-loop placement, cursor init.
// One block, 1024 threads, ~49 nodes per thread.
#define SCAN_T 1024
#define PER_T  ((NN + SCAN_T - 1) / SCAN_T)   // 49
__global__ void csr_scan_kernel() {
    __shared__ int sh[SCAN_T];
    int t = threadIdx.x;
    int base = t * PER_T;

    int run = 0;
#pragma unroll 7
    for (int i = 0; i < PER_T; i++) {
        int idx = base + i;
        if (idx < NN) run += g_counts[idx] + 1;   // +1 self loop
    }
    sh[t] = run;
    __syncthreads();
    for (int off = 1; off < SCAN_T; off <<= 1) {
        int v = (t >= off) ? sh[t - off] : 0;
        __syncthreads();
        sh[t] += v;
        __syncthreads();
    }
    int pos = sh[t] - run;   // exclusive base for this thread's range
    if (t == 0) g_rowptr[0] = 0;
#pragma unroll 7
    for (int i = 0; i < PER_T; i++) {
        int idx = base + i;
        if (idx < NN) {
            int c = g_counts[idx] + 1;
            int begin = pos;
            pos += c;
            g_rowptr[idx + 1] = pos;
            g_csrsrc[begin] = idx;      // self loop first
            g_counts[idx] = begin + 1;  // scatter cursor
        }
    }
}

__global__ void scatter_kernel(const int* __restrict__ src,
                               const int* __restrict__ dst) {
    int e = blockIdx.x * blockDim.x + threadIdx.x;
    if (e < EE) {
        int p = atomicAdd(&g_counts[dst[e]], 1);
        g_csrsrc[p] = src[e];
    }
}

// ---------------- aggregation: layer 1 (C=32), warp per dst node ------------
// Single pass: softmax stabilized by the self-loop logit (shift-invariant).
__global__ void agg1_kernel(const float* __restrict__ h,
                            const float* __restrict__ asrc,
                            const float* __restrict__ adst,
                            const float* __restrict__ bias,
                            float* __restrict__ out) {
    int warp = (blockIdx.x * blockDim.x + threadIdx.x) >> 5;
    int lane = threadIdx.x & 31;
    if (warp >= NN) return;

    int beg = g_rowptr[warp];
    int end = g_rowptr[warp + 1];
    int hsel = lane >> 3;   // head for first float4 chunk; second is hsel+4

    float adst_l = 0.f, aself_l = 0.f;
    if (lane < HEADS) {
        float as = asrc[warp * HEADS + lane];
        adst_l = adst[warp * HEADS + lane];
        float tt = as + adst_l;
        aself_l = (tt > 0.f) ? tt : NEG * tt;   // self-loop logit = stabilizer
    }

    float denom_l = 0.f;
    float4 acc0 = make_float4(0.f, 0.f, 0.f, 0.f);
    float4 acc1 = make_float4(0.f, 0.f, 0.f, 0.f);

    for (int j = beg; j < end; j++) {
        int s = g_csrsrc[j];
        float ex = 0.f;
        if (lane < HEADS) {
            float a = asrc[s * HEADS + lane] + adst_l;
            a = (a > 0.f) ? a : NEG * a;
            ex = __expf(fminf(a - aself_l, 60.f));
            denom_l += ex;
        }
        float e0 = __shfl_sync(0xffffffffu, ex, hsel);
        float e1 = __shfl_sync(0xffffffffu, ex, hsel + 4);
        const float4* hp = (const float4*)(h + (size_t)s * HC1);
        float4 v0 = hp[lane];
        float4 v1 = hp[32 + lane];
        acc0.x = fmaf(v0.x, e0, acc0.x); acc0.y = fmaf(v0.y, e0, acc0.y);
        acc0.z = fmaf(v0.z, e0, acc0.z); acc0.w = fmaf(v0.w, e0, acc0.w);
        acc1.x = fmaf(v1.x, e1, acc1.x); acc1.y = fmaf(v1.y, e1, acc1.y);
        acc1.z = fmaf(v1.z, e1, acc1.z); acc1.w = fmaf(v1.w, e1, acc1.w);
    }

    float d0 = __shfl_sync(0xffffffffu, denom_l, hsel) + 1e-16f;
    float d1 = __shfl_sync(0xffffffffu, denom_l, hsel + 4) + 1e-16f;
    const float4* b4 = (const float4*)bias;
    float4 bb0 = b4[lane], bb1 = b4[32 + lane];

    float4 o0, o1;
    o0.x = acc0.x / d0 + bb0.x; o0.y = acc0.y / d0 + bb0.y;
    o0.z = acc0.z / d0 + bb0.z; o0.w = acc0.w / d0 + bb0.w;
    o1.x = acc1.x / d1 + bb1.x; o1.y = acc1.y / d1 + bb1.y;
    o1.z = acc1.z / d1 + bb1.z; o1.w = acc1.w / d1 + bb1.w;
    o0.x = (o0.x > 0.f) ? o0.x : NEG * o0.x; o0.y = (o0.y > 0.f) ? o0.y : NEG * o0.y;
    o0.z = (o0.z > 0.f) ? o0.z : NEG * o0.z; o0.w = (o0.w > 0.f) ? o0.w : NEG * o0.w;
    o1.x = (o1.x > 0.f) ? o1.x : NEG * o1.x; o1.y = (o1.y > 0.f) ? o1.y : NEG * o1.y;
    o1.z = (o1.z > 0.f) ? o1.z : NEG * o1.z; o1.w = (o1.w > 0.f) ? o1.w : NEG * o1.w;

    float4* op = (float4*)(out + (size_t)warp * HC1);
    op[lane] = o0;
    op[32 + lane] = o1;
}

// ---------------- aggregation: layer 2 (C=4), warp per dst node -------------
__global__ void agg2_kernel(const float* __restrict__ h,
                            const float* __restrict__ asrc,
                            const float* __restrict__ adst,
                            const float* __restrict__ bias,
                            float* __restrict__ out) {
    int warp = (blockIdx.x * blockDim.x + threadIdx.x) >> 5;
    int lane = threadIdx.x & 31;
    if (warp >= NN) return;

    int beg = g_rowptr[warp];
    int end = g_rowptr[warp + 1];
    int hh = lane >> 2;

    float as_d = asrc[warp * HEADS + hh];
    float adst_l = adst[warp * HEADS + hh];
    float tt = as_d + adst_l;
    float aself = (tt > 0.f) ? tt : NEG * tt;

    float denom_l = 0.f;
    float acc = 0.f;
    for (int j = beg; j < end; j++) {
        int s = g_csrsrc[j];
        float a = asrc[s * HEADS + hh] + adst_l;
        a = (a > 0.f) ? a : NEG * a;
        float ex = __expf(fminf(a - aself, 60.f));
        denom_l += ex;
        acc = fmaf(h[(size_t)s * HC2 + lane], ex, acc);
    }

    out[(size_t)warp * HC2 + lane] = acc / (denom_l + 1e-16f) + bias[lane];
}

// ---------------- launch ------------------------------------------------------
extern "C" void kernel_launch(void* const* d_in, const int* in_sizes, int n_in,
                              void* d_out, int out_size) {
    const float* x      = (const float*)d_in[0];
    const int*   ei     = (const int*)d_in[1];
    const float* W1     = (const float*)d_in[2];
    const float* a_src1 = (const float*)d_in[3];
    const float* a_dst1 = (const float*)d_in[4];
    const float* b1     = (const float*)d_in[5];
    const float* W2     = (const float*)d_in[6];
    const float* a_src2 = (const float*)d_in[7];
    const float* a_dst2 = (const float*)d_in[8];
    const float* b2     = (const float*)d_in[9];
    float* out = (float*)d_out;

    const int* src = ei;
    const int* dst = ei + EE;

    float *h1, *o1, *h2, *as1, *ad1, *as2, *ad2;
    int *cnts;
    cudaGetSymbolAddress((void**)&h1,  g_h1);
    cudaGetSymbolAddress((void**)&o1,  g_o1);
    cudaGetSymbolAddress((void**)&h2,  g_h2);
    cudaGetSymbolAddress((void**)&as1, g_asrc1);
    cudaGetSymbolAddress((void**)&ad1, g_adst1);
    cudaGetSymbolAddress((void**)&as2, g_asrc2);
    cudaGetSymbolAddress((void**)&ad2, g_adst2);
    cudaGetSymbolAddress((void**)&cnts, g_counts);

    // --- CSR build (4 nodes: memset, count, fused scan+place, scatter) ---
    cudaMemsetAsync(cnts, 0, NN * sizeof(int));
    count_kernel<<<(EE + 255) / 256, 256>>>(dst);
    csr_scan_kernel<<<1, SCAN_T>>>();
    scatter_kernel<<<(EE + 255) / 256, 256>>>(src, dst);

    // --- layer 1 ---
    {
        dim3 grid(HC1 / 128, (NN + 127) / 128);
        sgemm_kernel<128, 128, 32, 8, 8><<<grid, 256>>>(NN, HC1, FIN, x, W1, h1);
    }
    alphas_kernel<HID><<<(NN * HEADS + 255) / 256, 256>>>(h1, a_src1, a_dst1, as1, ad1);
    agg1_kernel<<<(NN * 32 + 255) / 256, 256>>>(h1, as1, ad1, b1, o1);

    // --- layer 2 ---
    {
        dim3 grid(HC2 / 32, (NN + 127) / 128);
        sgemm_kernel<128, 32, 32, 8, 4><<<grid, 128>>>(NN, HC2, HC1, o1, W2, h2);
    }
    alphas_kernel<OUTC><<<(NN * HEADS + 255) / 256, 256>>>(h2, a_src2, a_dst2, as2, ad2);
    agg2_kernel<<<(NN * 32 + 255) / 256, 256>>>(h2, as2, ad2, b2, out);
}

// round 4
// speedup vs baseline: 1.2708x; 1.2708x over previous
#include <cuda_runtime.h>
#include <cuda_bf16.h>
#include <math.h>

// Problem constants (fixed shapes)
#define NN   50000
#define EE   800000
#define FIN  128
#define HEADS 8
#define HID  32
#define OUTC 4
#define HC1  (HEADS*HID)   // 256
#define HC2  (HEADS*OUTC)  // 32
#define NEG  0.2f

#define SCAN_B 1024
#define NBLK   ((NN + SCAN_B - 1) / SCAN_B)   // 49

// ---------------- scratch (__device__ globals; no runtime allocation) -------
__device__ float g_h1[NN * HC1];        // x @ W1
__device__ float g_o1[NN * HC1];        // layer-1 output (bias + lrelu applied)
__device__ float g_h2[NN * HC2];        // o1 @ W2
__device__ float g_asrc1[NN * HEADS], g_adst1[NN * HEADS];
__device__ float g_asrc2[NN * HEADS], g_adst2[NN * HEADS];
__device__ int   g_rowptr[NN + 1];
__device__ int   g_counts[NN];          // histogram, then scatter cursor
__device__ int   g_csrsrc[EE + NN];
__device__ int   g_blocksums[NBLK + 1];
__device__ int   g_blockoffs[NBLK + 1];

// ---------------- SGEMM: C[M,N] = A[M,K] @ B[K,N], row-major ----------------
template<int BM, int BN, int BK, int TM, int TN>
__global__ void sgemm_kernel(int M, int N, int K,
                             const float* __restrict__ A,
                             const float* __restrict__ B,
                             float* __restrict__ C) {
    constexpr int THREADS = (BM / TM) * (BN / TN);
    constexpr int KV = BK / 4;
    constexpr int NV = BN / 4;
    __shared__ float As[BK][BM + 4];
    __shared__ float Bs[BK][BN + 4];

    const int tid = threadIdx.x;
    const int blockRow = blockIdx.y * BM;
    const int blockCol = blockIdx.x * BN;
    const int tCol = (tid % (BN / TN)) * TN;
    const int tRow = (tid / (BN / TN)) * TM;

    float acc[TM][TN];
#pragma unroll
    for (int i = 0; i < TM; i++)
#pragma unroll
        for (int j = 0; j < TN; j++) acc[i][j] = 0.f;

    for (int k0 = 0; k0 < K; k0 += BK) {
#pragma unroll
        for (int i = tid; i < BM * KV; i += THREADS) {
            int m = i / KV, k4 = i % KV;
            int gm = blockRow + m;
            float4 v = make_float4(0.f, 0.f, 0.f, 0.f);
            if (gm < M) v = *(const float4*)&A[(size_t)gm * K + k0 + k4 * 4];
            As[k4 * 4 + 0][m] = v.x;
            As[k4 * 4 + 1][m] = v.y;
            As[k4 * 4 + 2][m] = v.z;
            As[k4 * 4 + 3][m] = v.w;
        }
#pragma unroll
        for (int i = tid; i < BK * NV; i += THREADS) {
            int k = i / NV, n4 = i % NV;
            *(float4*)&Bs[k][n4 * 4] =
                *(const float4*)&B[(size_t)(k0 + k) * N + blockCol + n4 * 4];
        }
        __syncthreads();

#pragma unroll
        for (int kk = 0; kk < BK; kk++) {
            float ra[TM], rb[TN];
#pragma unroll
            for (int im = 0; im < TM / 4; im++) {
                float4 a4 = *(const float4*)&As[kk][tRow + im * 4];
                ra[im * 4 + 0] = a4.x; ra[im * 4 + 1] = a4.y;
                ra[im * 4 + 2] = a4.z; ra[im * 4 + 3] = a4.w;
            }
#pragma unroll
            for (int jn = 0; jn < TN / 4; jn++) {
                float4 b4 = *(const float4*)&Bs[kk][tCol + jn * 4];
                rb[jn * 4 + 0] = b4.x; rb[jn * 4 + 1] = b4.y;
                rb[jn * 4 + 2] = b4.z; rb[jn * 4 + 3] = b4.w;
            }
#pragma unroll
            for (int i = 0; i < TM; i++)
#pragma unroll
                for (int j = 0; j < TN; j++)
                    acc[i][j] = fmaf(ra[i], rb[j], acc[i][j]);
        }
        __syncthreads();
    }

#pragma unroll
    for (int i = 0; i < TM; i++) {
        int gm = blockRow + tRow + i;
        if (gm < M) {
#pragma unroll
            for (int j4 = 0; j4 < TN / 4; j4++) {
                float4 v = make_float4(acc[i][j4 * 4 + 0], acc[i][j4 * 4 + 1],
                                       acc[i][j4 * 4 + 2], acc[i][j4 * 4 + 3]);
                *(float4*)&C[(size_t)gm * N + blockCol + tCol + j4 * 4] = v;
            }
        }
    }
}

// ---------------- alpha dot products: asrc[n,h], adst[n,h] ------------------
template<int C>
__global__ void alphas_kernel(const float* __restrict__ h,
                              const float* __restrict__ a_src,
                              const float* __restrict__ a_dst,
                              float* __restrict__ asrc,
                              float* __restrict__ adst) {
    int i = blockIdx.x * blockDim.x + threadIdx.x;   // i = n*HEADS + head
    if (i >= NN * HEADS) return;
    int hh = i & (HEADS - 1);
    const float4* hp = (const float4*)(h + (size_t)(i >> 3) * (HEADS * C) + hh * C);
    const float4* s4 = (const float4*)(a_src + hh * C);
    const float4* d4 = (const float4*)(a_dst + hh * C);
    float s1 = 0.f, s2 = 0.f;
#pragma unroll
    for (int c = 0; c < C / 4; c++) {
        float4 v = hp[c];
        float4 a = s4[c];
        float4 b = d4[c];
        s1 = fmaf(v.x, a.x, fmaf(v.y, a.y, fmaf(v.z, a.z, fmaf(v.w, a.w, s1))));
        s2 = fmaf(v.x, b.x, fmaf(v.y, b.y, fmaf(v.z, b.z, fmaf(v.w, b.w, s2))));
    }
    asrc[i] = s1;
    adst[i] = s2;
}

// ---------------- CSR construction (parallel chain, round-2 proven) ---------
__global__ void count_kernel(const int* __restrict__ dst) {
    int e = blockIdx.x * blockDim.x + threadIdx.x;
    if (e < EE) atomicAdd(&g_counts[dst[e]], 1);
}

__global__ void scan_blocks_kernel() {
    __shared__ int sh[SCAN_B];
    int t = threadIdx.x;
    int i = blockIdx.x * SCAN_B + t;
    int v = (i < NN) ? (g_counts[i] + 1) : 0;   // +1 self loop
    sh[t] = v;
    __syncthreads();
    for (int off = 1; off < SCAN_B; off <<= 1) {
        int x = (t >= off) ? sh[t - off] : 0;
        __syncthreads();
        sh[t] += x;
        __syncthreads();
    }
    if (i < NN) g_rowptr[i + 1] = sh[t];
    if (t == SCAN_B - 1) g_blocksums[blockIdx.x] = sh[t];
}

__global__ void scan_sums_kernel() {
    __shared__ int sh[64];
    int t = threadIdx.x;
    int v = (t < NBLK) ? g_blocksums[t] : 0;
    sh[t] = v;
    __syncthreads();
    for (int off = 1; off < 64; off <<= 1) {
        int x = (t >= off) ? sh[t - off] : 0;
        __syncthreads();
        sh[t] += x;
        __syncthreads();
    }
    if (t < NBLK) g_blockoffs[t] = sh[t] - v;  // exclusive
    if (t == 0) g_rowptr[0] = 0;
}

// add block offsets + place self loop + init cursor (fused, parallel)
__global__ void scan_add_place_kernel() {
    int i = blockIdx.x * blockDim.x + threadIdx.x;
    if (i < NN) {
        int e = g_rowptr[i + 1] + g_blockoffs[i / SCAN_B];
        g_rowptr[i + 1] = e;
        // begin of row i: need rowptr[i]; recompute via counts: begin = e - (counts[i]+1)
        int begin = e - (g_counts[i] + 1);
        g_csrsrc[begin] = i;        // self loop first
        g_counts[i] = begin + 1;    // scatter cursor
    }
}

__global__ void scatter_kernel(const int* __restrict__ src,
                               const int* __restrict__ dst) {
    int e = blockIdx.x * blockDim.x + threadIdx.x;
    if (e < EE) {
        int p = atomicAdd(&g_counts[dst[e]], 1);
        g_csrsrc[p] = src[e];
    }
}

// ---------------- aggregation: layer 1 (C=32), warp per dst node ------------
// Single pass: softmax stabilized by the self-loop logit (shift-invariant).
__global__ void agg1_kernel(const float* __restrict__ h,
                            const float* __restrict__ asrc,
                            const float* __restrict__ adst,
                            const float* __restrict__ bias,
                            float* __restrict__ out) {
    int warp = (blockIdx.x * blockDim.x + threadIdx.x) >> 5;
    int lane = threadIdx.x & 31;
    if (warp >= NN) return;

    int beg = g_rowptr[warp];
    int end = g_rowptr[warp + 1];
    int hsel = lane >> 3;   // head for first float4 chunk; second is hsel+4

    float adst_l = 0.f, aself_l = 0.f;
    if (lane < HEADS) {
        float as = asrc[warp * HEADS + lane];
        adst_l = adst[warp * HEADS + lane];
        float tt = as + adst_l;
        aself_l = (tt > 0.f) ? tt : NEG * tt;   // self-loop logit = stabilizer
    }

    float denom_l = 0.f;
    float4 acc0 = make_float4(0.f, 0.f, 0.f, 0.f);
    float4 acc1 = make_float4(0.f, 0.f, 0.f, 0.f);

    for (int j = beg; j < end; j++) {
        int s = g_csrsrc[j];
        float ex = 0.f;
        if (lane < HEADS) {
            float a = asrc[s * HEADS + lane] + adst_l;
            a = (a > 0.f) ? a : NEG * a;
            ex = __expf(fminf(a - aself_l, 60.f));
            denom_l += ex;
        }
        float e0 = __shfl_sync(0xffffffffu, ex, hsel);
        float e1 = __shfl_sync(0xffffffffu, ex, hsel + 4);
        const float4* hp = (const float4*)(h + (size_t)s * HC1);
        float4 v0 = hp[lane];
        float4 v1 = hp[32 + lane];
        acc0.x = fmaf(v0.x, e0, acc0.x); acc0.y = fmaf(v0.y, e0, acc0.y);
        acc0.z = fmaf(v0.z, e0, acc0.z); acc0.w = fmaf(v0.w, e0, acc0.w);
        acc1.x = fmaf(v1.x, e1, acc1.x); acc1.y = fmaf(v1.y, e1, acc1.y);
        acc1.z = fmaf(v1.z, e1, acc1.z); acc1.w = fmaf(v1.w, e1, acc1.w);
    }

    float d0 = __shfl_sync(0xffffffffu, denom_l, hsel) + 1e-16f;
    float d1 = __shfl_sync(0xffffffffu, denom_l, hsel + 4) + 1e-16f;
    const float4* b4 = (const float4*)bias;
    float4 bb0 = b4[lane], bb1 = b4[32 + lane];

    float4 o0, o1;
    o0.x = acc0.x / d0 + bb0.x; o0.y = acc0.y / d0 + bb0.y;
    o0.z = acc0.z / d0 + bb0.z; o0.w = acc0.w / d0 + bb0.w;
    o1.x = acc1.x / d1 + bb1.x; o1.y = acc1.y / d1 + bb1.y;
    o1.z = acc1.z / d1 + bb1.z; o1.w = acc1.w / d1 + bb1.w;
    o0.x = (o0.x > 0.f) ? o0.x : NEG * o0.x; o0.y = (o0.y > 0.f) ? o0.y : NEG * o0.y;
    o0.z = (o0.z > 0.f) ? o0.z : NEG * o0.z; o0.w = (o0.w > 0.f) ? o0.w : NEG * o0.w;
    o1.x = (o1.x > 0.f) ? o1.x : NEG * o1.x; o1.y = (o1.y > 0.f) ? o1.y : NEG * o1.y;
    o1.z = (o1.z > 0.f) ? o1.z : NEG * o1.z; o1.w = (o1.w > 0.f) ? o1.w : NEG * o1.w;

    float4* op = (float4*)(out + (size_t)warp * HC1);
    op[lane] = o0;
    op[32 + lane] = o1;
}

// ---------------- aggregation: layer 2 (C=4), warp per dst node -------------
__global__ void agg2_kernel(const float* __restrict__ h,
                            const float* __restrict__ asrc,
                            const float* __restrict__ adst,
                            const float* __restrict__ bias,
                            float* __restrict__ out) {
    int warp = (blockIdx.x * blockDim.x + threadIdx.x) >> 5;
    int lane = threadIdx.x & 31;
    if (warp >= NN) return;

    int beg = g_rowptr[warp];
    int end = g_rowptr[warp + 1];
    int hh = lane >> 2;

    float as_d = asrc[warp * HEADS + hh];
    float adst_l = adst[warp * HEADS + hh];
    float tt = as_d + adst_l;
    float aself = (tt > 0.f) ? tt : NEG * tt;

    float denom_l = 0.f;
    float acc = 0.f;
    for (int j = beg; j < end; j++) {
        int s = g_csrsrc[j];
        float a = asrc[s * HEADS + hh] + adst_l;
        a = (a > 0.f) ? a : NEG * a;
        float ex = __expf(fminf(a - aself, 60.f));
        denom_l += ex;
        acc = fmaf(h[(size_t)s * HC2 + lane], ex, acc);
    }

    out[(size_t)warp * HC2 + lane] = acc / (denom_l + 1e-16f) + bias[lane];
}

// ---------------- launch ------------------------------------------------------
extern "C" void kernel_launch(void* const* d_in, const int* in_sizes, int n_in,
                              void* d_out, int out_size) {
    const float* x      = (const float*)d_in[0];
    const int*   ei     = (const int*)d_in[1];
    const float* W1     = (const float*)d_in[2];
    const float* a_src1 = (const float*)d_in[3];
    const float* a_dst1 = (const float*)d_in[4];
    const float* b1     = (const float*)d_in[5];
    const float* W2     = (const float*)d_in[6];
    const float* a_src2 = (const float*)d_in[7];
    const float* a_dst2 = (const float*)d_in[8];
    const float* b2     = (const float*)d_in[9];
    float* out = (float*)d_out;

    const int* src = ei;
    const int* dst = ei + EE;

    float *h1, *o1, *h2, *as1, *ad1, *as2, *ad2;
    int *cnts;
    cudaGetSymbolAddress((void**)&h1,  g_h1);
    cudaGetSymbolAddress((void**)&o1,  g_o1);
    cudaGetSymbolAddress((void**)&h2,  g_h2);
    cudaGetSymbolAddress((void**)&as1, g_asrc1);
    cudaGetSymbolAddress((void**)&ad1, g_adst1);
    cudaGetSymbolAddress((void**)&as2, g_asrc2);
    cudaGetSymbolAddress((void**)&ad2, g_adst2);
    cudaGetSymbolAddress((void**)&cnts, g_counts);

    // --- CSR build (parallel chain) ---
    cudaMemsetAsync(cnts, 0, NN * sizeof(int));
    count_kernel<<<(EE + 255) / 256, 256>>>(dst);
    scan_blocks_kernel<<<NBLK, SCAN_B>>>();
    scan_sums_kernel<<<1, 64>>>();
    scan_add_place_kernel<<<(NN + 255) / 256, 256>>>();
    scatter_kernel<<<(EE + 255) / 256, 256>>>(src, dst);

    // --- layer 1 ---
    {
        dim3 grid(HC1 / 128, (NN + 127) / 128);
        sgemm_kernel<128, 128, 16, 8, 8><<<grid, 256>>>(NN, HC1, FIN, x, W1, h1);
    }
    alphas_kernel<HID><<<(NN * HEADS + 255) / 256, 256>>>(h1, a_src1, a_dst1, as1, ad1);
    agg1_kernel<<<(NN * 32 + 255) / 256, 256>>>(h1, as1, ad1, b1, o1);

    // --- layer 2 ---
    {
        dim3 grid(HC2 / 32, (NN + 127) / 128);
        sgemm_kernel<128, 32, 32, 8, 4><<<grid, 128>>>(NN, HC2, HC1, o1, W2, h2);
    }
    alphas_kernel<OUTC><<<(NN * HEADS + 255) / 256, 256>>>(h2, a_src2, a_dst2, as2, ad2);
    agg2_kernel<<<(NN * 32 + 255) / 256, 256>>>(h2, as2, ad2, b2, out);
}

// round 5
// speedup vs baseline: 1.3295x; 1.0461x over previous
#include <cuda_runtime.h>
#include <cuda_bf16.h>
#include <math.h>

// Problem constants (fixed shapes)
#define NN   50000
#define EE   800000
#define FIN  128
#define HEADS 8
#define HID  32
#define OUTC 4
#define HC1  (HEADS*HID)   // 256
#define HC2  (HEADS*OUTC)  // 32
#define NEG  0.2f

#define SCAN_B 1024
#define NBLK   ((NN + SCAN_B - 1) / SCAN_B)   // 49

// ---------------- scratch (__device__ globals; no runtime allocation) -------
__device__ float g_h1[NN * HC1];
__device__ float g_o1[NN * HC1];
__device__ float g_h2[NN * HC2];
__device__ float g_asrc1[NN * HEADS], g_adst1[NN * HEADS];
__device__ float g_asrc2[NN * HEADS], g_adst2[NN * HEADS];
__device__ int   g_rowptr[NN + 1];
__device__ int   g_counts[NN];          // histogram, then scatter cursor
__device__ int   g_csrsrc[EE + NN];
__device__ int   g_blocksums[NBLK + 1];

// ------------- double-buffered SGEMM: C[M,N] = A[M,K] @ B[K,N] --------------
template<int BM, int BN, int BK, int TM, int TN>
__global__ void sgemm_db_kernel(int M, int N, int K,
                                const float* __restrict__ A,
                                const float* __restrict__ B,
                                float* __restrict__ C) {
    constexpr int THREADS = (BM / TM) * (BN / TN);
    constexpr int KV = BK / 4;
    constexpr int NV = BN / 4;
    constexpr int AL = (BM * KV) / THREADS;   // float4 A-loads per thread
    constexpr int BL = (BK * NV) / THREADS;   // float4 B-loads per thread
    static_assert(AL * THREADS == BM * KV, "A tile divisibility");
    static_assert(BL * THREADS == BK * NV, "B tile divisibility");

    __shared__ float As[2][BK][BM + 4];
    __shared__ float Bs[2][BK][BN + 4];

    const int tid = threadIdx.x;
    const int blockRow = blockIdx.y * BM;
    const int blockCol = blockIdx.x * BN;
    const int tCol = (tid % (BN / TN)) * TN;
    const int tRow = (tid / (BN / TN)) * TM;

    float acc[TM][TN];
#pragma unroll
    for (int i = 0; i < TM; i++)
#pragma unroll
        for (int j = 0; j < TN; j++) acc[i][j] = 0.f;

    float4 ar[AL], br[BL];

    // --- prologue: load tile 0 into buffer 0 ---
#pragma unroll
    for (int l = 0; l < AL; l++) {
        int i = tid + l * THREADS;
        int m = i / KV, k4 = i % KV;
        int gm = blockRow + m;
        ar[l] = (gm < M) ? *(const float4*)&A[(size_t)gm * K + k4 * 4]
                         : make_float4(0.f, 0.f, 0.f, 0.f);
    }
#pragma unroll
    for (int l = 0; l < BL; l++) {
        int i = tid + l * THREADS;
        int k = i / NV, n4 = i % NV;
        br[l] = *(const float4*)&B[(size_t)k * N + blockCol + n4 * 4];
    }
#pragma unroll
    for (int l = 0; l < AL; l++) {
        int i = tid + l * THREADS;
        int m = i / KV, k4 = i % KV;
        As[0][k4 * 4 + 0][m] = ar[l].x;
        As[0][k4 * 4 + 1][m] = ar[l].y;
        As[0][k4 * 4 + 2][m] = ar[l].z;
        As[0][k4 * 4 + 3][m] = ar[l].w;
    }
#pragma unroll
    for (int l = 0; l < BL; l++) {
        int i = tid + l * THREADS;
        int k = i / NV, n4 = i % NV;
        *(float4*)&Bs[0][k][n4 * 4] = br[l];
    }
    __syncthreads();

    const int nT = K / BK;
    for (int t = 0; t < nT; t++) {
        const int cur = t & 1;
        // prefetch next tile into registers (overlaps compute)
        if (t + 1 < nT) {
            const int k0 = (t + 1) * BK;
#pragma unroll
            for (int l = 0; l < AL; l++) {
                int i = tid + l * THREADS;
                int m = i / KV, k4 = i % KV;
                int gm = blockRow + m;
                ar[l] = (gm < M) ? *(const float4*)&A[(size_t)gm * K + k0 + k4 * 4]
                                 : make_float4(0.f, 0.f, 0.f, 0.f);
            }
#pragma unroll
            for (int l = 0; l < BL; l++) {
                int i = tid + l * THREADS;
                int k = i / NV, n4 = i % NV;
                br[l] = *(const float4*)&B[(size_t)(k0 + k) * N + blockCol + n4 * 4];
            }
        }

        // compute on current buffer
#pragma unroll
        for (int kk = 0; kk < BK; kk++) {
            float ra[TM], rb[TN];
#pragma unroll
            for (int im = 0; im < TM / 4; im++) {
                float4 a4 = *(const float4*)&As[cur][kk][tRow + im * 4];
                ra[im * 4 + 0] = a4.x; ra[im * 4 + 1] = a4.y;
                ra[im * 4 + 2] = a4.z; ra[im * 4 + 3] = a4.w;
            }
#pragma unroll
            for (int jn = 0; jn < TN / 4; jn++) {
                float4 b4 = *(const float4*)&Bs[cur][kk][tCol + jn * 4];
                rb[jn * 4 + 0] = b4.x; rb[jn * 4 + 1] = b4.y;
                rb[jn * 4 + 2] = b4.z; rb[jn * 4 + 3] = b4.w;
            }
#pragma unroll
            for (int i = 0; i < TM; i++)
#pragma unroll
                for (int j = 0; j < TN; j++)
                    acc[i][j] = fmaf(ra[i], rb[j], acc[i][j]);
        }

        // store prefetched tile into the other buffer, single barrier per tile
        if (t + 1 < nT) {
            const int nxt = cur ^ 1;
#pragma unroll
            for (int l = 0; l < AL; l++) {
                int i = tid + l * THREADS;
                int m = i / KV, k4 = i % KV;
                As[nxt][k4 * 4 + 0][m] = ar[l].x;
                As[nxt][k4 * 4 + 1][m] = ar[l].y;
                As[nxt][k4 * 4 + 2][m] = ar[l].z;
                As[nxt][k4 * 4 + 3][m] = ar[l].w;
            }
#pragma unroll
            for (int l = 0; l < BL; l++) {
                int i = tid + l * THREADS;
                int k = i / NV, n4 = i % NV;
                *(float4*)&Bs[nxt][k][n4 * 4] = br[l];
            }
            __syncthreads();
        }
    }

#pragma unroll
    for (int i = 0; i < TM; i++) {
        int gm = blockRow + tRow + i;
        if (gm < M) {
#pragma unroll
            for (int j4 = 0; j4 < TN / 4; j4++) {
                float4 v = make_float4(acc[i][j4 * 4 + 0], acc[i][j4 * 4 + 1],
                                       acc[i][j4 * 4 + 2], acc[i][j4 * 4 + 3]);
                *(float4*)&C[(size_t)gm * N + blockCol + tCol + j4 * 4] = v;
            }
        }
    }
}

// ---------------- alpha dot products: asrc[n,h], adst[n,h] ------------------
template<int C>
__global__ void alphas_kernel(const float* __restrict__ h,
                              const float* __restrict__ a_src,
                              const float* __restrict__ a_dst,
                              float* __restrict__ asrc,
                              float* __restrict__ adst) {
    int i = blockIdx.x * blockDim.x + threadIdx.x;   // i = n*HEADS + head
    if (i >= NN * HEADS) return;
    int hh = i & (HEADS - 1);
    const float4* hp = (const float4*)(h + (size_t)(i >> 3) * (HEADS * C) + hh * C);
    const float4* s4 = (const float4*)(a_src + hh * C);
    const float4* d4 = (const float4*)(a_dst + hh * C);
    float s1 = 0.f, s2 = 0.f;
#pragma unroll
    for (int c = 0; c < C / 4; c++) {
        float4 v = hp[c];
        float4 a = s4[c];
        float4 b = d4[c];
        s1 = fmaf(v.x, a.x, fmaf(v.y, a.y, fmaf(v.z, a.z, fmaf(v.w, a.w, s1))));
        s2 = fmaf(v.x, b.x, fmaf(v.y, b.y, fmaf(v.z, b.z, fmaf(v.w, b.w, s2))));
    }
    asrc[i] = s1;
    adst[i] = s2;
}

// ---------------- CSR construction ------------------------------------------
__global__ void count_kernel(const int* __restrict__ dst) {
    int e = blockIdx.x * blockDim.x + threadIdx.x;
    if (e < EE) atomicAdd(&g_counts[dst[e]], 1);
}

__global__ void scan_blocks_kernel() {
    __shared__ int sh[SCAN_B];
    int t = threadIdx.x;
    int i = blockIdx.x * SCAN_B + t;
    int v = (i < NN) ? (g_counts[i] + 1) : 0;   // +1 self loop
    sh[t] = v;
    __syncthreads();
    for (int off = 1; off < SCAN_B; off <<= 1) {
        int x = (t >= off) ? sh[t - off] : 0;
        __syncthreads();
        sh[t] += x;
        __syncthreads();
    }
    if (i < NN) g_rowptr[i + 1] = sh[t];
    if (t == SCAN_B - 1) g_blocksums[blockIdx.x] = sh[t];
}

// Fused: per-block prefix over blocksums (warp reduce) + rowptr finalize +
// self-loop placement + cursor init. Block b's 256 nodes all lie in scan
// block sb = b/4, so one offset per block suffices.
__global__ void scan_finalize_kernel() {
    __shared__ int s_off;
    int t = threadIdx.x;
    int sb = (blockIdx.x * 256) / SCAN_B;   // scan-block index of this block
    if (t < 32) {
        int v = 0;
        if (t < sb) v += g_blocksums[t];
        if (t + 32 < sb) v += g_blocksums[t + 32];
#pragma unroll
        for (int off = 16; off > 0; off >>= 1)
            v += __shfl_down_sync(0xffffffffu, v, off);
        if (t == 0) s_off = v;
    }
    __syncthreads();
    int i = blockIdx.x * 256 + t;
    if (i == 0) g_rowptr[0] = 0;
    if (i < NN) {
        int e = g_rowptr[i + 1] + s_off;
        g_rowptr[i + 1] = e;
        int begin = e - (g_counts[i] + 1);
        g_csrsrc[begin] = i;        // self loop first
        g_counts[i] = begin + 1;    // scatter cursor
    }
}

__global__ void scatter_kernel(const int* __restrict__ src,
                               const int* __restrict__ dst) {
    int e = blockIdx.x * blockDim.x + threadIdx.x;
    if (e < EE) {
        int p = atomicAdd(&g_counts[dst[e]], 1);
        g_csrsrc[p] = src[e];
    }
}

// ---------------- aggregation: layer 1 (C=32), warp per dst node ------------
__global__ void agg1_kernel(const float* __restrict__ h,
                            const float* __restrict__ asrc,
                            const float* __restrict__ adst,
                            const float* __restrict__ bias,
                            float* __restrict__ out) {
    int warp = (blockIdx.x * blockDim.x + threadIdx.x) >> 5;
    int lane = threadIdx.x & 31;
    if (warp >= NN) return;

    int beg = g_rowptr[warp];
    int end = g_rowptr[warp + 1];
    int hsel = lane >> 3;

    float adst_l = 0.f, aself_l = 0.f;
    if (lane < HEADS) {
        float as = asrc[warp * HEADS + lane];
        adst_l = adst[warp * HEADS + lane];
        float tt = as + adst_l;
        aself_l = (tt > 0.f) ? tt : NEG * tt;   // self-loop logit = stabilizer
    }

    float denom_l = 0.f;
    float4 acc0 = make_float4(0.f, 0.f, 0.f, 0.f);
    float4 acc1 = make_float4(0.f, 0.f, 0.f, 0.f);

    for (int j = beg; j < end; j++) {
        int s = g_csrsrc[j];
        float ex = 0.f;
        if (lane < HEADS) {
            float a = asrc[s * HEADS + lane] + adst_l;
            a = (a > 0.f) ? a : NEG * a;
            ex = __expf(fminf(a - aself_l, 60.f));
            denom_l += ex;
        }
        float e0 = __shfl_sync(0xffffffffu, ex, hsel);
        float e1 = __shfl_sync(0xffffffffu, ex, hsel + 4);
        const float4* hp = (const float4*)(h + (size_t)s * HC1);
        float4 v0 = hp[lane];
        float4 v1 = hp[32 + lane];
        acc0.x = fmaf(v0.x, e0, acc0.x); acc0.y = fmaf(v0.y, e0, acc0.y);
        acc0.z = fmaf(v0.z, e0, acc0.z); acc0.w = fmaf(v0.w, e0, acc0.w);
        acc1.x = fmaf(v1.x, e1, acc1.x); acc1.y = fmaf(v1.y, e1, acc1.y);
        acc1.z = fmaf(v1.z, e1, acc1.z); acc1.w = fmaf(v1.w, e1, acc1.w);
    }

    float d0 = __shfl_sync(0xffffffffu, denom_l, hsel) + 1e-16f;
    float d1 = __shfl_sync(0xffffffffu, denom_l, hsel + 4) + 1e-16f;
    const float4* b4 = (const float4*)bias;
    float4 bb0 = b4[lane], bb1 = b4[32 + lane];

    float4 o0, o1;
    o0.x = acc0.x / d0 + bb0.x; o0.y = acc0.y / d0 + bb0.y;
    o0.z = acc0.z / d0 + bb0.z; o0.w = acc0.w / d0 + bb0.w;
    o1.x = acc1.x / d1 + bb1.x; o1.y = acc1.y / d1 + bb1.y;
    o1.z = acc1.z / d1 + bb1.z; o1.w = acc1.w / d1 + bb1.w;
    o0.x = (o0.x > 0.f) ? o0.x : NEG * o0.x; o0.y = (o0.y > 0.f) ? o0.y : NEG * o0.y;
    o0.z = (o0.z > 0.f) ? o0.z : NEG * o0.z; o0.w = (o0.w > 0.f) ? o0.w : NEG * o0.w;
    o1.x = (o1.x > 0.f) ? o1.x : NEG * o1.x; o1.y = (o1.y > 0.f) ? o1.y : NEG * o1.y;
    o1.z = (o1.z > 0.f) ? o1.z : NEG * o1.z; o1.w = (o1.w > 0.f) ? o1.w : NEG * o1.w;

    float4* op = (float4*)(out + (size_t)warp * HC1);
    op[lane] = o0;
    op[32 + lane] = o1;
}

// ---------------- aggregation: layer 2 (C=4), warp per dst node -------------
__global__ void agg2_kernel(const float* __restrict__ h,
                            const float* __restrict__ asrc,
                            const float* __restrict__ adst,
                            const float* __restrict__ bias,
                            float* __restrict__ out) {
    int warp = (blockIdx.x * blockDim.x + threadIdx.x) >> 5;
    int lane = threadIdx.x & 31;
    if (warp >= NN) return;

    int beg = g_rowptr[warp];
    int end = g_rowptr[warp + 1];
    int hh = lane >> 2;

    float as_d = asrc[warp * HEADS + hh];
    float adst_l = adst[warp * HEADS + hh];
    float tt = as_d + adst_l;
    float aself = (tt > 0.f) ? tt : NEG * tt;

    float denom_l = 0.f;
    float acc = 0.f;
    for (int j = beg; j < end; j++) {
        int s = g_csrsrc[j];
        float a = asrc[s * HEADS + hh] + adst_l;
        a = (a > 0.f) ? a : NEG * a;
        float ex = __expf(fminf(a - aself, 60.f));
        denom_l += ex;
        acc = fmaf(h[(size_t)s * HC2 + lane], ex, acc);
    }

    out[(size_t)warp * HC2 + lane] = acc / (denom_l + 1e-16f) + bias[lane];
}

// ---------------- launch ------------------------------------------------------
extern "C" void kernel_launch(void* const* d_in, const int* in_sizes, int n_in,
                              void* d_out, int out_size) {
    const float* x      = (const float*)d_in[0];
    const int*   ei     = (const int*)d_in[1];
    const float* W1     = (const float*)d_in[2];
    const float* a_src1 = (const float*)d_in[3];
    const float* a_dst1 = (const float*)d_in[4];
    const float* b1     = (const float*)d_in[5];
    const float* W2     = (const float*)d_in[6];
    const float* a_src2 = (const float*)d_in[7];
    const float* a_dst2 = (const float*)d_in[8];
    const float* b2     = (const float*)d_in[9];
    float* out = (float*)d_out;

    const int* src = ei;
    const int* dst = ei + EE;

    float *h1, *o1, *h2, *as1, *ad1, *as2, *ad2;
    int *cnts;
    cudaGetSymbolAddress((void**)&h1,  g_h1);
    cudaGetSymbolAddress((void**)&o1,  g_o1);
    cudaGetSymbolAddress((void**)&h2,  g_h2);
    cudaGetSymbolAddress((void**)&as1, g_asrc1);
    cudaGetSymbolAddress((void**)&ad1, g_adst1);
    cudaGetSymbolAddress((void**)&as2, g_asrc2);
    cudaGetSymbolAddress((void**)&ad2, g_adst2);
    cudaGetSymbolAddress((void**)&cnts, g_counts);

    // --- CSR build (5 nodes) ---
    cudaMemsetAsync(cnts, 0, NN * sizeof(int));
    count_kernel<<<(EE + 255) / 256, 256>>>(dst);
    scan_blocks_kernel<<<NBLK, SCAN_B>>>();
    scan_finalize_kernel<<<(NN + 255) / 256, 256>>>();
    scatter_kernel<<<(EE + 255) / 256, 256>>>(src, dst);

    // --- layer 1 ---
    {
        dim3 grid(HC1 / 128, (NN + 127) / 128);
        sgemm_db_kernel<128, 128, 16, 8, 8><<<grid, 256>>>(NN, HC1, FIN, x, W1, h1);
    }
    alphas_kernel<HID><<<(NN * HEADS + 255) / 256, 256>>>(h1, a_src1, a_dst1, as1, ad1);
    agg1_kernel<<<(NN * 32 + 255) / 256, 256>>>(h1, as1, ad1, b1, o1);

    // --- layer 2 ---
    {
        dim3 grid(HC2 / 32, (NN + 127) / 128);
        sgemm_db_kernel<128, 32, 32, 8, 4><<<grid, 128>>>(NN, HC2, HC1, o1, W2, h2);
    }
    alphas_kernel<OUTC><<<(NN * HEADS + 255) / 256, 256>>>(h2, a_src2, a_dst2, as2, ad2);
    agg2_kernel<<<(NN * 32 + 255) / 256, 256>>>(h2, as2, ad2, b2, out);
}

// round 6
// speedup vs baseline: 1.3853x; 1.0420x over previous
#include <cuda_runtime.h>
#include <cuda_bf16.h>
#include <math.h>

// Problem constants (fixed shapes)
#define NN   50000
#define EE   800000
#define FIN  128
#define HEADS 8
#define HID  32
#define OUTC 4
#define HC1  (HEADS*HID)   // 256
#define HC2  (HEADS*OUTC)  // 32
#define NEG  0.2f

#define SCAN_B 1024
#define NBLK   ((NN + SCAN_B - 1) / SCAN_B)   // 49

// ---------------- scratch (__device__ globals; no runtime allocation) -------
__device__ float g_h1[NN * HC1];
__device__ float g_o1[NN * HC1];
__device__ float g_h2[NN * HC2];
__device__ float g_asrc1[NN * HEADS], g_adst1[NN * HEADS];
__device__ float g_asrc2[NN * HEADS], g_adst2[NN * HEADS];
__device__ int   g_rowptr[NN + 1];
__device__ int   g_counts[NN];          // histogram, then scatter cursor
__device__ int   g_csrsrc[EE + NN];
__device__ int   g_blocksums[NBLK + 1];

// ------------- double-buffered SGEMM: C[M,N] = A[M,K] @ B[K,N] --------------
template<int BM, int BN, int BK, int TM, int TN>
__global__ void sgemm_db_kernel(int M, int N, int K,
                                const float* __restrict__ A,
                                const float* __restrict__ B,
                                float* __restrict__ C) {
    constexpr int THREADS = (BM / TM) * (BN / TN);
    constexpr int KV = BK / 4;
    constexpr int NV = BN / 4;
    constexpr int AL = (BM * KV) / THREADS;
    constexpr int BL = (BK * NV) / THREADS;
    static_assert(AL * THREADS == BM * KV, "A tile divisibility");
    static_assert(BL * THREADS == BK * NV, "B tile divisibility");

    __shared__ float As[2][BK][BM + 4];
    __shared__ float Bs[2][BK][BN + 4];

    const int tid = threadIdx.x;
    const int blockRow = blockIdx.y * BM;
    const int blockCol = blockIdx.x * BN;
    const int tCol = (tid % (BN / TN)) * TN;
    const int tRow = (tid / (BN / TN)) * TM;

    float acc[TM][TN];
#pragma unroll
    for (int i = 0; i < TM; i++)
#pragma unroll
        for (int j = 0; j < TN; j++) acc[i][j] = 0.f;

    float4 ar[AL], br[BL];

#pragma unroll
    for (int l = 0; l < AL; l++) {
        int i = tid + l * THREADS;
        int m = i / KV, k4 = i % KV;
        int gm = blockRow + m;
        ar[l] = (gm < M) ? *(const float4*)&A[(size_t)gm * K + k4 * 4]
                         : make_float4(0.f, 0.f, 0.f, 0.f);
    }
#pragma unroll
    for (int l = 0; l < BL; l++) {
        int i = tid + l * THREADS;
        int k = i / NV, n4 = i % NV;
        br[l] = *(const float4*)&B[(size_t)k * N + blockCol + n4 * 4];
    }
#pragma unroll
    for (int l = 0; l < AL; l++) {
        int i = tid + l * THREADS;
        int m = i / KV, k4 = i % KV;
        As[0][k4 * 4 + 0][m] = ar[l].x;
        As[0][k4 * 4 + 1][m] = ar[l].y;
        As[0][k4 * 4 + 2][m] = ar[l].z;
        As[0][k4 * 4 + 3][m] = ar[l].w;
    }
#pragma unroll
    for (int l = 0; l < BL; l++) {
        int i = tid + l * THREADS;
        int k = i / NV, n4 = i % NV;
        *(float4*)&Bs[0][k][n4 * 4] = br[l];
    }
    __syncthreads();

    const int nT = K / BK;
    for (int t = 0; t < nT; t++) {
        const int cur = t & 1;
        if (t + 1 < nT) {
            const int k0 = (t + 1) * BK;
#pragma unroll
            for (int l = 0; l < AL; l++) {
                int i = tid + l * THREADS;
                int m = i / KV, k4 = i % KV;
                int gm = blockRow + m;
                ar[l] = (gm < M) ? *(const float4*)&A[(size_t)gm * K + k0 + k4 * 4]
                                 : make_float4(0.f, 0.f, 0.f, 0.f);
            }
#pragma unroll
            for (int l = 0; l < BL; l++) {
                int i = tid + l * THREADS;
                int k = i / NV, n4 = i % NV;
                br[l] = *(const float4*)&B[(size_t)(k0 + k) * N + blockCol + n4 * 4];
            }
        }

#pragma unroll
        for (int kk = 0; kk < BK; kk++) {
            float ra[TM], rb[TN];
#pragma unroll
            for (int im = 0; im < TM / 4; im++) {
                float4 a4 = *(const float4*)&As[cur][kk][tRow + im * 4];
                ra[im * 4 + 0] = a4.x; ra[im * 4 + 1] = a4.y;
                ra[im * 4 + 2] = a4.z; ra[im * 4 + 3] = a4.w;
            }
#pragma unroll
            for (int jn = 0; jn < TN / 4; jn++) {
                float4 b4 = *(const float4*)&Bs[cur][kk][tCol + jn * 4];
                rb[jn * 4 + 0] = b4.x; rb[jn * 4 + 1] = b4.y;
                rb[jn * 4 + 2] = b4.z; rb[jn * 4 + 3] = b4.w;
            }
#pragma unroll
            for (int i = 0; i < TM; i++)
#pragma unroll
                for (int j = 0; j < TN; j++)
                    acc[i][j] = fmaf(ra[i], rb[j], acc[i][j]);
        }

        if (t + 1 < nT) {
            const int nxt = cur ^ 1;
#pragma unroll
            for (int l = 0; l < AL; l++) {
                int i = tid + l * THREADS;
                int m = i / KV, k4 = i % KV;
                As[nxt][k4 * 4 + 0][m] = ar[l].x;
                As[nxt][k4 * 4 + 1][m] = ar[l].y;
                As[nxt][k4 * 4 + 2][m] = ar[l].z;
                As[nxt][k4 * 4 + 3][m] = ar[l].w;
            }
#pragma unroll
            for (int l = 0; l < BL; l++) {
                int i = tid + l * THREADS;
                int k = i / NV, n4 = i % NV;
                *(float4*)&Bs[nxt][k][n4 * 4] = br[l];
            }
            __syncthreads();
        }
    }

#pragma unroll
    for (int i = 0; i < TM; i++) {
        int gm = blockRow + tRow + i;
        if (gm < M) {
#pragma unroll
            for (int j4 = 0; j4 < TN / 4; j4++) {
                float4 v = make_float4(acc[i][j4 * 4 + 0], acc[i][j4 * 4 + 1],
                                       acc[i][j4 * 4 + 2], acc[i][j4 * 4 + 3]);
                *(float4*)&C[(size_t)gm * N + blockCol + tCol + j4 * 4] = v;
            }
        }
    }
}

// ---------------- alpha dot products: asrc[n,h], adst[n,h] ------------------
template<int C>
__global__ void alphas_kernel(const float* __restrict__ h,
                              const float* __restrict__ a_src,
                              const float* __restrict__ a_dst,
                              float* __restrict__ asrc,
                              float* __restrict__ adst) {
    int i = blockIdx.x * blockDim.x + threadIdx.x;
    if (i >= NN * HEADS) return;
    int hh = i & (HEADS - 1);
    const float4* hp = (const float4*)(h + (size_t)(i >> 3) * (HEADS * C) + hh * C);
    const float4* s4 = (const float4*)(a_src + hh * C);
    const float4* d4 = (const float4*)(a_dst + hh * C);
    float s1 = 0.f, s2 = 0.f;
#pragma unroll
    for (int c = 0; c < C / 4; c++) {
        float4 v = hp[c];
        float4 a = s4[c];
        float4 b = d4[c];
        s1 = fmaf(v.x, a.x, fmaf(v.y, a.y, fmaf(v.z, a.z, fmaf(v.w, a.w, s1))));
        s2 = fmaf(v.x, b.x, fmaf(v.y, b.y, fmaf(v.z, b.z, fmaf(v.w, b.w, s2))));
    }
    asrc[i] = s1;
    adst[i] = s2;
}

// ---------------- CSR construction ------------------------------------------
__global__ void count_kernel(const int* __restrict__ dst) {
    int e = blockIdx.x * blockDim.x + threadIdx.x;
    if (e < EE) atomicAdd(&g_counts[dst[e]], 1);
}

__global__ void scan_blocks_kernel() {
    __shared__ int sh[SCAN_B];
    int t = threadIdx.x;
    int i = blockIdx.x * SCAN_B + t;
    int v = (i < NN) ? (g_counts[i] + 1) : 0;   // +1 self loop
    sh[t] = v;
    __syncthreads();
    for (int off = 1; off < SCAN_B; off <<= 1) {
        int x = (t >= off) ? sh[t - off] : 0;
        __syncthreads();
        sh[t] += x;
        __syncthreads();
    }
    if (i < NN) g_rowptr[i + 1] = sh[t];
    if (t == SCAN_B - 1) g_blocksums[blockIdx.x] = sh[t];
}

__global__ void scan_finalize_kernel() {
    __shared__ int s_off;
    int t = threadIdx.x;
    int sb = (blockIdx.x * 256) / SCAN_B;
    if (t < 32) {
        int v = 0;
        if (t < sb) v += g_blocksums[t];
        if (t + 32 < sb) v += g_blocksums[t + 32];
#pragma unroll
        for (int off = 16; off > 0; off >>= 1)
            v += __shfl_down_sync(0xffffffffu, v, off);
        if (t == 0) s_off = v;
    }
    __syncthreads();
    int i = blockIdx.x * 256 + t;
    if (i == 0) g_rowptr[0] = 0;
    if (i < NN) {
        int e = g_rowptr[i + 1] + s_off;
        g_rowptr[i + 1] = e;
        int begin = e - (g_counts[i] + 1);
        g_csrsrc[begin] = i;        // self loop first
        g_counts[i] = begin + 1;    // scatter cursor
    }
}

__global__ void scatter_kernel(const int* __restrict__ src,
                               const int* __restrict__ dst) {
    int e = blockIdx.x * blockDim.x + threadIdx.x;
    if (e < EE) {
        int p = atomicAdd(&g_counts[dst[e]], 1);
        g_csrsrc[p] = src[e];
    }
}

// ---------------- aggregation: layer 1 (C=32), warp per dst node ------------
__global__ void agg1_kernel(const float* __restrict__ h,
                            const float* __restrict__ asrc,
                            const float* __restrict__ adst,
                            const float* __restrict__ bias,
                            float* __restrict__ out) {
    int warp = (blockIdx.x * blockDim.x + threadIdx.x) >> 5;
    int lane = threadIdx.x & 31;
    if (warp >= NN) return;

    int beg = g_rowptr[warp];
    int end = g_rowptr[warp + 1];
    int hsel = lane >> 3;

    float adst_l = 0.f, aself_l = 0.f;
    if (lane < HEADS) {
        float as = asrc[warp * HEADS + lane];
        adst_l = adst[warp * HEADS + lane];
        float tt = as + adst_l;
        aself_l = (tt > 0.f) ? tt : NEG * tt;   // self-loop logit = stabilizer
    }

    float denom_l = 0.f;
    float4 acc0 = make_float4(0.f, 0.f, 0.f, 0.f);
    float4 acc1 = make_float4(0.f, 0.f, 0.f, 0.f);

    for (int j = beg; j < end; j++) {
        int s = g_csrsrc[j];
        float ex = 0.f;
        if (lane < HEADS) {
            float a = asrc[s * HEADS + lane] + adst_l;
            a = (a > 0.f) ? a : NEG * a;
            ex = __expf(fminf(a - aself_l, 60.f));
            denom_l += ex;
        }
        float e0 = __shfl_sync(0xffffffffu, ex, hsel);
        float e1 = __shfl_sync(0xffffffffu, ex, hsel + 4);
        const float4* hp = (const float4*)(h + (size_t)s * HC1);
        float4 v0 = hp[lane];
        float4 v1 = hp[32 + lane];
        acc0.x = fmaf(v0.x, e0, acc0.x); acc0.y = fmaf(v0.y, e0, acc0.y);
        acc0.z = fmaf(v0.z, e0, acc0.z); acc0.w = fmaf(v0.w, e0, acc0.w);
        acc1.x = fmaf(v1.x, e1, acc1.x); acc1.y = fmaf(v1.y, e1, acc1.y);
        acc1.z = fmaf(v1.z, e1, acc1.z); acc1.w = fmaf(v1.w, e1, acc1.w);
    }

    float d0 = __shfl_sync(0xffffffffu, denom_l, hsel) + 1e-16f;
    float d1 = __shfl_sync(0xffffffffu, denom_l, hsel + 4) + 1e-16f;
    const float4* b4 = (const float4*)bias;
    float4 bb0 = b4[lane], bb1 = b4[32 + lane];

    float4 o0, o1;
    o0.x = acc0.x / d0 + bb0.x; o0.y = acc0.y / d0 + bb0.y;
    o0.z = acc0.z / d0 + bb0.z; o0.w = acc0.w / d0 + bb0.w;
    o1.x = acc1.x / d1 + bb1.x; o1.y = acc1.y / d1 + bb1.y;
    o1.z = acc1.z / d1 + bb1.z; o1.w = acc1.w / d1 + bb1.w;
    o0.x = (o0.x > 0.f) ? o0.x : NEG * o0.x; o0.y = (o0.y > 0.f) ? o0.y : NEG * o0.y;
    o0.z = (o0.z > 0.f) ? o0.z : NEG * o0.z; o0.w = (o0.w > 0.f) ? o0.w : NEG * o0.w;
    o1.x = (o1.x > 0.f) ? o1.x : NEG * o1.x; o1.y = (o1.y > 0.f) ? o1.y : NEG * o1.y;
    o1.z = (o1.z > 0.f) ? o1.z : NEG * o1.z; o1.w = (o1.w > 0.f) ? o1.w : NEG * o1.w;

    float4* op = (float4*)(out + (size_t)warp * HC1);
    op[lane] = o0;
    op[32 + lane] = o1;
}

// ---------------- aggregation: layer 2 (C=4), warp per dst node -------------
__global__ void agg2_kernel(const float* __restrict__ h,
                            const float* __restrict__ asrc,
                            const float* __restrict__ adst,
                            const float* __restrict__ bias,
                            float* __restrict__ out) {
    int warp = (blockIdx.x * blockDim.x + threadIdx.x) >> 5;
    int lane = threadIdx.x & 31;
    if (warp >= NN) return;

    int beg = g_rowptr[warp];
    int end = g_rowptr[warp + 1];
    int hh = lane >> 2;

    float as_d = asrc[warp * HEADS + hh];
    float adst_l = adst[warp * HEADS + hh];
    float tt = as_d + adst_l;
    float aself = (tt > 0.f) ? tt : NEG * tt;

    float denom_l = 0.f;
    float acc = 0.f;
    for (int j = beg; j < end; j++) {
        int s = g_csrsrc[j];
        float a = asrc[s * HEADS + hh] + adst_l;
        a = (a > 0.f) ? a : NEG * a;
        float ex = __expf(fminf(a - aself, 60.f));
        denom_l += ex;
        acc = fmaf(h[(size_t)s * HC2 + lane], ex, acc);
    }

    out[(size_t)warp * HC2 + lane] = acc / (denom_l + 1e-16f) + bias[lane];
}

// ---------------- launch ------------------------------------------------------
extern "C" void kernel_launch(void* const* d_in, const int* in_sizes, int n_in,
                              void* d_out, int out_size) {
    const float* x      = (const float*)d_in[0];
    const int*   ei     = (const int*)d_in[1];
    const float* W1     = (const float*)d_in[2];
    const float* a_src1 = (const float*)d_in[3];
    const float* a_dst1 = (const float*)d_in[4];
    const float* b1     = (const float*)d_in[5];
    const float* W2     = (const float*)d_in[6];
    const float* a_src2 = (const float*)d_in[7];
    const float* a_dst2 = (const float*)d_in[8];
    const float* b2     = (const float*)d_in[9];
    float* out = (float*)d_out;

    const int* src = ei;
    const int* dst = ei + EE;

    float *h1, *o1, *h2, *as1, *ad1, *as2, *ad2;
    int *cnts;
    cudaGetSymbolAddress((void**)&h1,  g_h1);
    cudaGetSymbolAddress((void**)&o1,  g_o1);
    cudaGetSymbolAddress((void**)&h2,  g_h2);
    cudaGetSymbolAddress((void**)&as1, g_asrc1);
    cudaGetSymbolAddress((void**)&ad1, g_adst1);
    cudaGetSymbolAddress((void**)&as2, g_asrc2);
    cudaGetSymbolAddress((void**)&ad2, g_adst2);
    cudaGetSymbolAddress((void**)&cnts, g_counts);

    // One-time stream/event creation (no device memory involved).
    static cudaStream_t s2 = nullptr;
    static cudaEvent_t evFork = nullptr, evJoin = nullptr;
    if (s2 == nullptr) {
        cudaStreamCreateWithFlags(&s2, cudaStreamNonBlocking);
        cudaEventCreateWithFlags(&evFork, cudaEventDisableTiming);
        cudaEventCreateWithFlags(&evJoin, cudaEventDisableTiming);
    }

    // --- fork: CSR build on s2, GEMM1 chain on main stream -------------------
    cudaEventRecord(evFork, 0);
    cudaStreamWaitEvent(s2, evFork, 0);

    cudaMemsetAsync(cnts, 0, NN * sizeof(int), s2);
    count_kernel<<<(EE + 255) / 256, 256, 0, s2>>>(dst);
    scan_blocks_kernel<<<NBLK, SCAN_B, 0, s2>>>();
    scan_finalize_kernel<<<(NN + 255) / 256, 256, 0, s2>>>();
    scatter_kernel<<<(EE + 255) / 256, 256, 0, s2>>>(src, dst);
    cudaEventRecord(evJoin, s2);

    // main stream: GEMM1 + alphas1 (independent of CSR)
    {
        dim3 grid(HC1 / 128, (NN + 127) / 128);
        sgemm_db_kernel<128, 128, 16, 8, 8><<<grid, 256>>>(NN, HC1, FIN, x, W1, h1);
    }
    alphas_kernel<HID><<<(NN * HEADS + 255) / 256, 256>>>(h1, a_src1, a_dst1, as1, ad1);

    // --- join: agg1 needs both branches --------------------------------------
    cudaStreamWaitEvent(0, evJoin, 0);
    agg1_kernel<<<(NN * 32 + 255) / 256, 256>>>(h1, as1, ad1, b1, o1);

    // --- layer 2 ---
    {
        dim3 grid(HC2 / 32, (NN + 127) / 128);
        sgemm_db_kernel<128, 32, 32, 8, 4><<<grid, 128>>>(NN, HC2, HC1, o1, W2, h2);
    }
    alphas_kernel<OUTC><<<(NN * HEADS + 255) / 256, 256>>>(h2, a_src2, a_dst2, as2, ad2);
    agg2_kernel<<<(NN * 32 + 255) / 256, 256>>>(h2, as2, ad2, b2, out);
}

// round 7
// speedup vs baseline: 1.4819x; 1.0698x over previous
#include <cuda_runtime.h>
#include <cuda_bf16.h>
#include <math.h>

// Problem constants (fixed shapes)
#define NN   50000
#define EE   800000
#define FIN  128
#define HEADS 8
#define HID  32
#define OUTC 4
#define HC1  (HEADS*HID)   // 256
#define HC2  (HEADS*OUTC)  // 32
#define NEG  0.2f

#define SCAN_B 1024
#define NBLK   ((NN + SCAN_B - 1) / SCAN_B)   // 49

// ---------------- scratch (__device__ globals; no runtime allocation) -------
__device__ float g_h1[NN * HC1];
__device__ float g_o1[NN * HC1];
__device__ float g_h2[NN * HC2];
__device__ float g_asrc1[NN * HEADS], g_adst1[NN * HEADS];
__device__ float g_asrc2[NN * HEADS], g_adst2[NN * HEADS];
__device__ int   g_rowptr[NN + 1];
__device__ int   g_counts[NN];          // histogram, then scatter cursor
__device__ int   g_csrsrc[EE + NN];
__device__ int   g_blocksums[NBLK + 1];

// ---------------- tf32 helpers ----------------------------------------------
__device__ __forceinline__ float tf32r(float v) {
    float r;
    asm("cvt.rna.tf32.f32 %0, %1;" : "=f"(r) : "f"(v));
    return r;
}
__device__ __forceinline__ void mma8(float* c, const unsigned* a, const unsigned* b) {
    asm volatile(
        "mma.sync.aligned.m16n8k8.row.col.f32.tf32.tf32.f32 "
        "{%0,%1,%2,%3}, {%4,%5,%6,%7}, {%8,%9}, {%0,%1,%2,%3};\n"
        : "+f"(c[0]), "+f"(c[1]), "+f"(c[2]), "+f"(c[3])
        : "r"(a[0]), "r"(a[1]), "r"(a[2]), "r"(a[3]), "r"(b[0]), "r"(b[1]));
}

// ------------- 3xTF32 tensor-core GEMM: C[M,N] = A[M,K] @ B[K,N] ------------
// BM=128, BK=32, 256 threads (8 warps: 4 m-warps x 2 n-warps).
// Warp tile: 32 x (BN/2). Fragments per PTX m16n8k8 tf32 layout.
// Smem tiles hold float2{hi, lo} splits; row pitches chosen so pitch*8B = 32 (mod 128).
template<int BN>
__global__ __launch_bounds__(256, 2)
void gemm_tf32_kernel(int M, int N, int K,
                      const float* __restrict__ A,
                      const float* __restrict__ B,
                      float* __restrict__ C) {
    constexpr int BM = 128, BK = 32;
    constexpr int NT  = BN / 16;       // n8-tiles per warp
    constexpr int BKP = 36;            // A row pitch (float2)
    constexpr int BNP = BN + 4;        // B row pitch (float2): 132 / 36, both ==4 mod 16
    constexpr int BNV = BN / 4;        // float4 per B row
    constexpr int BLD = (BK * BNV) / 256;

    extern __shared__ float2 smem2[];
    float2* As = smem2;                       // [BM][BKP]
    float2* Bs = smem2 + BM * BKP;            // [BK][BNP]

    const int tid = threadIdx.x;
    const int wid = tid >> 5, lane = tid & 31;
    const int gq = lane >> 2, tig = lane & 3;
    const int warp_m = wid & 3, warp_n = wid >> 2;
    const int blockRow = blockIdx.y * BM;
    const int blockCol = blockIdx.x * BN;

    float acc[2][NT][4];
#pragma unroll
    for (int i = 0; i < 2; i++)
#pragma unroll
        for (int j = 0; j < NT; j++)
#pragma unroll
            for (int r = 0; r < 4; r++) acc[i][j][r] = 0.f;

    for (int k0 = 0; k0 < K; k0 += BK) {
        if (k0) __syncthreads();
        // stage A chunk (128x32) with hi/lo split
#pragma unroll
        for (int l = 0; l < 4; l++) {
            int idx = tid + l * 256;
            int m = idx >> 3, kv = idx & 7;
            int gm = blockRow + m;
            float4 v = (gm < M) ? *(const float4*)&A[(size_t)gm * K + k0 + kv * 4]
                                : make_float4(0.f, 0.f, 0.f, 0.f);
            float hx = tf32r(v.x), hy = tf32r(v.y), hz = tf32r(v.z), hw = tf32r(v.w);
            As[m * BKP + kv * 4 + 0] = make_float2(hx, tf32r(v.x - hx));
            As[m * BKP + kv * 4 + 1] = make_float2(hy, tf32r(v.y - hy));
            As[m * BKP + kv * 4 + 2] = make_float2(hz, tf32r(v.z - hz));
            As[m * BKP + kv * 4 + 3] = make_float2(hw, tf32r(v.w - hw));
        }
        // stage B chunk (32xBN)
#pragma unroll
        for (int l = 0; l < BLD; l++) {
            int idx = tid + l * 256;
            int k = idx / BNV, nv = idx % BNV;
            float4 v = *(const float4*)&B[(size_t)(k0 + k) * N + blockCol + nv * 4];
            float hx = tf32r(v.x), hy = tf32r(v.y), hz = tf32r(v.z), hw = tf32r(v.w);
            Bs[k * BNP + nv * 4 + 0] = make_float2(hx, tf32r(v.x - hx));
            Bs[k * BNP + nv * 4 + 1] = make_float2(hy, tf32r(v.y - hy));
            Bs[k * BNP + nv * 4 + 2] = make_float2(hz, tf32r(v.z - hz));
            Bs[k * BNP + nv * 4 + 3] = make_float2(hw, tf32r(v.w - hw));
        }
        __syncthreads();

#pragma unroll
        for (int ks = 0; ks < BK / 8; ks++) {
            const int kk = ks * 8;
            unsigned ah[2][4], al[2][4];
#pragma unroll
            for (int i = 0; i < 2; i++) {
                int m0 = warp_m * 32 + i * 16 + gq;
                float2 p0 = As[(m0)     * BKP + kk + tig];
                float2 p1 = As[(m0 + 8) * BKP + kk + tig];
                float2 p2 = As[(m0)     * BKP + kk + tig + 4];
                float2 p3 = As[(m0 + 8) * BKP + kk + tig + 4];
                ah[i][0] = __float_as_uint(p0.x); al[i][0] = __float_as_uint(p0.y);
                ah[i][1] = __float_as_uint(p1.x); al[i][1] = __float_as_uint(p1.y);
                ah[i][2] = __float_as_uint(p2.x); al[i][2] = __float_as_uint(p2.y);
                ah[i][3] = __float_as_uint(p3.x); al[i][3] = __float_as_uint(p3.y);
            }
#pragma unroll
            for (int j = 0; j < NT; j++) {
                int n = warp_n * (NT * 8) + j * 8 + gq;
                float2 q0 = Bs[(kk + tig)     * BNP + n];
                float2 q1 = Bs[(kk + tig + 4) * BNP + n];
                unsigned bh[2] = {__float_as_uint(q0.x), __float_as_uint(q1.x)};
                unsigned bl[2] = {__float_as_uint(q0.y), __float_as_uint(q1.y)};
#pragma unroll
                for (int i = 0; i < 2; i++) {
                    mma8(acc[i][j], ah[i], bh);
                    mma8(acc[i][j], ah[i], bl);
                    mma8(acc[i][j], al[i], bh);
                }
            }
        }
    }

    // epilogue: float2 stores
#pragma unroll
    for (int i = 0; i < 2; i++) {
#pragma unroll
        for (int j = 0; j < NT; j++) {
            int row0 = blockRow + warp_m * 32 + i * 16 + gq;
            int col  = blockCol + warp_n * (NT * 8) + j * 8 + 2 * tig;
            if (row0 < M)
                *(float2*)&C[(size_t)row0 * N + col] = make_float2(acc[i][j][0], acc[i][j][1]);
            if (row0 + 8 < M)
                *(float2*)&C[(size_t)(row0 + 8) * N + col] = make_float2(acc[i][j][2], acc[i][j][3]);
        }
    }
}

// ---------------- alpha dot products: asrc[n,h], adst[n,h] ------------------
template<int C>
__global__ void alphas_kernel(const float* __restrict__ h,
                              const float* __restrict__ a_src,
                              const float* __restrict__ a_dst,
                              float* __restrict__ asrc,
                              float* __restrict__ adst) {
    int i = blockIdx.x * blockDim.x + threadIdx.x;
    if (i >= NN * HEADS) return;
    int hh = i & (HEADS - 1);
    const float4* hp = (const float4*)(h + (size_t)(i >> 3) * (HEADS * C) + hh * C);
    const float4* s4 = (const float4*)(a_src + hh * C);
    const float4* d4 = (const float4*)(a_dst + hh * C);
    float s1 = 0.f, s2 = 0.f;
#pragma unroll
    for (int c = 0; c < C / 4; c++) {
        float4 v = hp[c];
        float4 a = s4[c];
        float4 b = d4[c];
        s1 = fmaf(v.x, a.x, fmaf(v.y, a.y, fmaf(v.z, a.z, fmaf(v.w, a.w, s1))));
        s2 = fmaf(v.x, b.x, fmaf(v.y, b.y, fmaf(v.z, b.z, fmaf(v.w, b.w, s2))));
    }
    asrc[i] = s1;
    adst[i] = s2;
}

// ---------------- CSR construction ------------------------------------------
__global__ void count_kernel(const int* __restrict__ dst) {
    int e = blockIdx.x * blockDim.x + threadIdx.x;
    if (e < EE) atomicAdd(&g_counts[dst[e]], 1);
}

__global__ void scan_blocks_kernel() {
    __shared__ int sh[SCAN_B];
    int t = threadIdx.x;
    int i = blockIdx.x * SCAN_B + t;
    int v = (i < NN) ? (g_counts[i] + 1) : 0;   // +1 self loop
    sh[t] = v;
    __syncthreads();
    for (int off = 1; off < SCAN_B; off <<= 1) {
        int x = (t >= off) ? sh[t - off] : 0;
        __syncthreads();
        sh[t] += x;
        __syncthreads();
    }
    if (i < NN) g_rowptr[i + 1] = sh[t];
    if (t == SCAN_B - 1) g_blocksums[blockIdx.x] = sh[t];
}

__global__ void scan_finalize_kernel() {
    __shared__ int s_off;
    int t = threadIdx.x;
    int sb = (blockIdx.x * 256) / SCAN_B;
    if (t < 32) {
        int v = 0;
        if (t < sb) v += g_blocksums[t];
        if (t + 32 < sb) v += g_blocksums[t + 32];
#pragma unroll
        for (int off = 16; off > 0; off >>= 1)
            v += __shfl_down_sync(0xffffffffu, v, off);
        if (t == 0) s_off = v;
    }
    __syncthreads();
    int i = blockIdx.x * 256 + t;
    if (i == 0) g_rowptr[0] = 0;
    if (i < NN) {
        int e = g_rowptr[i + 1] + s_off;
        g_rowptr[i + 1] = e;
        int begin = e - (g_counts[i] + 1);
        g_csrsrc[begin] = i;        // self loop first
        g_counts[i] = begin + 1;    // scatter cursor
    }
}

__global__ void scatter_kernel(const int* __restrict__ src,
                               const int* __restrict__ dst) {
    int e = blockIdx.x * blockDim.x + threadIdx.x;
    if (e < EE) {
        int p = atomicAdd(&g_counts[dst[e]], 1);
        g_csrsrc[p] = src[e];
    }
}

// ---------------- aggregation: layer 1 (C=32), warp per dst node ------------
__global__ void agg1_kernel(const float* __restrict__ h,
                            const float* __restrict__ asrc,
                            const float* __restrict__ adst,
                            const float* __restrict__ bias,
                            float* __restrict__ out) {
    int warp = (blockIdx.x * blockDim.x + threadIdx.x) >> 5;
    int lane = threadIdx.x & 31;
    if (warp >= NN) return;

    int beg = g_rowptr[warp];
    int end = g_rowptr[warp + 1];
    int hsel = lane >> 3;

    float adst_l = 0.f, aself_l = 0.f;
    if (lane < HEADS) {
        float as = asrc[warp * HEADS + lane];
        adst_l = adst[warp * HEADS + lane];
        float tt = as + adst_l;
        aself_l = (tt > 0.f) ? tt : NEG * tt;   // self-loop logit = stabilizer
    }

    float denom_l = 0.f;
    float4 acc0 = make_float4(0.f, 0.f, 0.f, 0.f);
    float4 acc1 = make_float4(0.f, 0.f, 0.f, 0.f);

    for (int j = beg; j < end; j++) {
        int s = g_csrsrc[j];
        float ex = 0.f;
        if (lane < HEADS) {
            float a = asrc[s * HEADS + lane] + adst_l;
            a = (a > 0.f) ? a : NEG * a;
            ex = __expf(fminf(a - aself_l, 60.f));
            denom_l += ex;
        }
        float e0 = __shfl_sync(0xffffffffu, ex, hsel);
        float e1 = __shfl_sync(0xffffffffu, ex, hsel + 4);
        const float4* hp = (const float4*)(h + (size_t)s * HC1);
        float4 v0 = hp[lane];
        float4 v1 = hp[32 + lane];
        acc0.x = fmaf(v0.x, e0, acc0.x); acc0.y = fmaf(v0.y, e0, acc0.y);
        acc0.z = fmaf(v0.z, e0, acc0.z); acc0.w = fmaf(v0.w, e0, acc0.w);
        acc1.x = fmaf(v1.x, e1, acc1.x); acc1.y = fmaf(v1.y, e1, acc1.y);
        acc1.z = fmaf(v1.z, e1, acc1.z); acc1.w = fmaf(v1.w, e1, acc1.w);
    }

    float d0 = __shfl_sync(0xffffffffu, denom_l, hsel) + 1e-16f;
    float d1 = __shfl_sync(0xffffffffu, denom_l, hsel + 4) + 1e-16f;
    const float4* b4 = (const float4*)bias;
    float4 bb0 = b4[lane], bb1 = b4[32 + lane];

    float4 o0, o1;
    o0.x = acc0.x / d0 + bb0.x; o0.y = acc0.y / d0 + bb0.y;
    o0.z = acc0.z / d0 + bb0.z; o0.w = acc0.w / d0 + bb0.w;
    o1.x = acc1.x / d1 + bb1.x; o1.y = acc1.y / d1 + bb1.y;
    o1.z = acc1.z / d1 + bb1.z; o1.w = acc1.w / d1 + bb1.w;
    o0.x = (o0.x > 0.f) ? o0.x : NEG * o0.x; o0.y = (o0.y > 0.f) ? o0.y : NEG * o0.y;
    o0.z = (o0.z > 0.f) ? o0.z : NEG * o0.z; o0.w = (o0.w > 0.f) ? o0.w : NEG * o0.w;
    o1.x = (o1.x > 0.f) ? o1.x : NEG * o1.x; o1.y = (o1.y > 0.f) ? o1.y : NEG * o1.y;
    o1.z = (o1.z > 0.f) ? o1.z : NEG * o1.z; o1.w = (o1.w > 0.f) ? o1.w : NEG * o1.w;

    float4* op = (float4*)(out + (size_t)warp * HC1);
    op[lane] = o0;
    op[32 + lane] = o1;
}

// ---------------- aggregation: layer 2 (C=4), warp per dst node -------------
__global__ void agg2_kernel(const float* __restrict__ h,
                            const float* __restrict__ asrc,
                            const float* __restrict__ adst,
                            const float* __restrict__ bias,
                            float* __restrict__ out) {
    int warp = (blockIdx.x * blockDim.x + threadIdx.x) >> 5;
    int lane = threadIdx.x & 31;
    if (warp >= NN) return;

    int beg = g_rowptr[warp];
    int end = g_rowptr[warp + 1];
    int hh = lane >> 2;

    float as_d = asrc[warp * HEADS + hh];
    float adst_l = adst[warp * HEADS + hh];
    float tt = as_d + adst_l;
    float aself = (tt > 0.f) ? tt : NEG * tt;

    float denom_l = 0.f;
    float acc = 0.f;
    for (int j = beg; j < end; j++) {
        int s = g_csrsrc[j];
        float a = asrc[s * HEADS + hh] + adst_l;
        a = (a > 0.f) ? a : NEG * a;
        float ex = __expf(fminf(a - aself, 60.f));
        denom_l += ex;
        acc = fmaf(h[(size_t)s * HC2 + lane], ex, acc);
    }

    out[(size_t)warp * HC2 + lane] = acc / (denom_l + 1e-16f) + bias[lane];
}

// ---------------- launch ------------------------------------------------------
extern "C" void kernel_launch(void* const* d_in, const int* in_sizes, int n_in,
                              void* d_out, int out_size) {
    const float* x      = (const float*)d_in[0];
    const int*   ei     = (const int*)d_in[1];
    const float* W1     = (const float*)d_in[2];
    const float* a_src1 = (const float*)d_in[3];
    const float* a_dst1 = (const float*)d_in[4];
    const float* b1     = (const float*)d_in[5];
    const float* W2     = (const float*)d_in[6];
    const float* a_src2 = (const float*)d_in[7];
    const float* a_dst2 = (const float*)d_in[8];
    const float* b2     = (const float*)d_in[9];
    float* out = (float*)d_out;

    const int* src = ei;
    const int* dst = ei + EE;

    float *h1, *o1, *h2, *as1, *ad1, *as2, *ad2;
    int *cnts;
    cudaGetSymbolAddress((void**)&h1,  g_h1);
    cudaGetSymbolAddress((void**)&o1,  g_o1);
    cudaGetSymbolAddress((void**)&h2,  g_h2);
    cudaGetSymbolAddress((void**)&as1, g_asrc1);
    cudaGetSymbolAddress((void**)&ad1, g_adst1);
    cudaGetSymbolAddress((void**)&as2, g_asrc2);
    cudaGetSymbolAddress((void**)&ad2, g_adst2);
    cudaGetSymbolAddress((void**)&cnts, g_counts);

    // smem sizes for the tf32 GEMMs
    const int smem1 = (128 * 36 + 32 * 132) * (int)sizeof(float2);  // 70656
    const int smem2sz = (128 * 36 + 32 * 36) * (int)sizeof(float2); // 46080
    cudaFuncSetAttribute(gemm_tf32_kernel<128>,
                         cudaFuncAttributeMaxDynamicSharedMemorySize, smem1);
    cudaFuncSetAttribute(gemm_tf32_kernel<32>,
                         cudaFuncAttributeMaxDynamicSharedMemorySize, smem2sz);

    // One-time stream/event creation (no device memory involved).
    static cudaStream_t s2 = nullptr;
    static cudaEvent_t evFork = nullptr, evJoin = nullptr;
    if (s2 == nullptr) {
        cudaStreamCreateWithFlags(&s2, cudaStreamNonBlocking);
        cudaEventCreateWithFlags(&evFork, cudaEventDisableTiming);
        cudaEventCreateWithFlags(&evJoin, cudaEventDisableTiming);
    }

    // --- fork: CSR build on s2, GEMM1 chain on main stream -------------------
    cudaEventRecord(evFork, 0);
    cudaStreamWaitEvent(s2, evFork, 0);

    cudaMemsetAsync(cnts, 0, NN * sizeof(int), s2);
    count_kernel<<<(EE + 255) / 256, 256, 0, s2>>>(dst);
    scan_blocks_kernel<<<NBLK, SCAN_B, 0, s2>>>();
    scan_finalize_kernel<<<(NN + 255) / 256, 256, 0, s2>>>();
    scatter_kernel<<<(EE + 255) / 256, 256, 0, s2>>>(src, dst);
    cudaEventRecord(evJoin, s2);

    // main stream: GEMM1 + alphas1 (independent of CSR)
    {
        dim3 grid(HC1 / 128, (NN + 127) / 128);
        gemm_tf32_kernel<128><<<grid, 256, smem1>>>(NN, HC1, FIN, x, W1, h1);
    }
    alphas_kernel<HID><<<(NN * HEADS + 255) / 256, 256>>>(h1, a_src1, a_dst1, as1, ad1);

    // --- join: agg1 needs both branches --------------------------------------
    cudaStreamWaitEvent(0, evJoin, 0);
    agg1_kernel<<<(NN * 32 + 255) / 256, 256>>>(h1, as1, ad1, b1, o1);

    // --- layer 2 ---
    {
        dim3 grid(1, (NN + 127) / 128);
        gemm_tf32_kernel<32><<<grid, 256, smem2sz>>>(NN, HC2, HC1, o1, W2, h2);
    }
    alphas_kernel<OUTC><<<(NN * HEADS + 255) / 256, 256>>>(h2, a_src2, a_dst2, as2, ad2);
    agg2_kernel<<<(NN * 32 + 255) / 256, 256>>>(h2, as2, ad2, b2, out);
}

// round 8
// speedup vs baseline: 1.6487x; 1.1125x over previous
#include <cuda_runtime.h>
#include <cuda_fp16.h>
#include <math.h>

// Problem constants (fixed shapes)
#define NN   50000
#define EE   800000
#define FIN  128
#define HEADS 8
#define HID  32
#define OUTC 4
#define HC1  (HEADS*HID)   // 256
#define HC2  (HEADS*OUTC)  // 32
#define NEG  0.2f

#define SCAN_B 1024
#define NBLK   ((NN + SCAN_B - 1) / SCAN_B)   // 49

// ---------------- scratch (__device__ globals; no runtime allocation) -------
__device__ float  g_h1[NN * HC1];
__device__ __half g_h1h[NN * HC1];      // fp16 copy of h1 for the agg1 gather
__device__ float  g_o1[NN * HC1];
__device__ float  g_h2[NN * HC2];
__device__ float  g_asrc1[NN * HEADS], g_adst1[NN * HEADS];
__device__ float  g_asrc2[NN * HEADS], g_adst2[NN * HEADS];
__device__ int    g_rowptr[NN + 1];
__device__ int    g_counts[NN];         // histogram, then scatter cursor
__device__ int    g_csrsrc[EE + NN];
__device__ int    g_blocksums[NBLK + 1];

// ---------------- tf32 helpers ----------------------------------------------
__device__ __forceinline__ float tf32r(float v) {
    float r;
    asm("cvt.rna.tf32.f32 %0, %1;" : "=f"(r) : "f"(v));
    return r;
}
__device__ __forceinline__ void mma8(float* c, const unsigned* a, const unsigned* b) {
    asm volatile(
        "mma.sync.aligned.m16n8k8.row.col.f32.tf32.tf32.f32 "
        "{%0,%1,%2,%3}, {%4,%5,%6,%7}, {%8,%9}, {%0,%1,%2,%3};\n"
        : "+f"(c[0]), "+f"(c[1]), "+f"(c[2]), "+f"(c[3])
        : "r"(a[0]), "r"(a[1]), "r"(a[2]), "r"(a[3]), "r"(b[0]), "r"(b[1]));
}

// ------------- 3xTF32 tensor-core GEMM: C[M,N] = A[M,K] @ B[K,N] ------------
template<int BN>
__global__ __launch_bounds__(256, 2)
void gemm_tf32_kernel(int M, int N, int K,
                      const float* __restrict__ A,
                      const float* __restrict__ B,
                      float* __restrict__ C) {
    constexpr int BM = 128, BK = 32;
    constexpr int NT  = BN / 16;
    constexpr int BKP = 36;
    constexpr int BNP = BN + 4;
    constexpr int BNV = BN / 4;
    constexpr int BLD = (BK * BNV) / 256;

    extern __shared__ float2 smem2[];
    float2* As = smem2;                       // [BM][BKP]
    float2* Bs = smem2 + BM * BKP;            // [BK][BNP]

    const int tid = threadIdx.x;
    const int wid = tid >> 5, lane = tid & 31;
    const int gq = lane >> 2, tig = lane & 3;
    const int warp_m = wid & 3, warp_n = wid >> 2;
    const int blockRow = blockIdx.y * BM;
    const int blockCol = blockIdx.x * BN;

    float acc[2][NT][4];
#pragma unroll
    for (int i = 0; i < 2; i++)
#pragma unroll
        for (int j = 0; j < NT; j++)
#pragma unroll
            for (int r = 0; r < 4; r++) acc[i][j][r] = 0.f;

    for (int k0 = 0; k0 < K; k0 += BK) {
        if (k0) __syncthreads();
#pragma unroll
        for (int l = 0; l < 4; l++) {
            int idx = tid + l * 256;
            int m = idx >> 3, kv = idx & 7;
            int gm = blockRow + m;
            float4 v = (gm < M) ? *(const float4*)&A[(size_t)gm * K + k0 + kv * 4]
                                : make_float4(0.f, 0.f, 0.f, 0.f);
            float hx = tf32r(v.x), hy = tf32r(v.y), hz = tf32r(v.z), hw = tf32r(v.w);
            As[m * BKP + kv * 4 + 0] = make_float2(hx, tf32r(v.x - hx));
            As[m * BKP + kv * 4 + 1] = make_float2(hy, tf32r(v.y - hy));
            As[m * BKP + kv * 4 + 2] = make_float2(hz, tf32r(v.z - hz));
            As[m * BKP + kv * 4 + 3] = make_float2(hw, tf32r(v.w - hw));
        }
#pragma unroll
        for (int l = 0; l < BLD; l++) {
            int idx = tid + l * 256;
            int k = idx / BNV, nv = idx % BNV;
            float4 v = *(const float4*)&B[(size_t)(k0 + k) * N + blockCol + nv * 4];
            float hx = tf32r(v.x), hy = tf32r(v.y), hz = tf32r(v.z), hw = tf32r(v.w);
            Bs[k * BNP + nv * 4 + 0] = make_float2(hx, tf32r(v.x - hx));
            Bs[k * BNP + nv * 4 + 1] = make_float2(hy, tf32r(v.y - hy));
            Bs[k * BNP + nv * 4 + 2] = make_float2(hz, tf32r(v.z - hz));
            Bs[k * BNP + nv * 4 + 3] = make_float2(hw, tf32r(v.w - hw));
        }
        __syncthreads();

#pragma unroll
        for (int ks = 0; ks < BK / 8; ks++) {
            const int kk = ks * 8;
            unsigned ah[2][4], al[2][4];
#pragma unroll
            for (int i = 0; i < 2; i++) {
                int m0 = warp_m * 32 + i * 16 + gq;
                float2 p0 = As[(m0)     * BKP + kk + tig];
                float2 p1 = As[(m0 + 8) * BKP + kk + tig];
                float2 p2 = As[(m0)     * BKP + kk + tig + 4];
                float2 p3 = As[(m0 + 8) * BKP + kk + tig + 4];
                ah[i][0] = __float_as_uint(p0.x); al[i][0] = __float_as_uint(p0.y);
                ah[i][1] = __float_as_uint(p1.x); al[i][1] = __float_as_uint(p1.y);
                ah[i][2] = __float_as_uint(p2.x); al[i][2] = __float_as_uint(p2.y);
                ah[i][3] = __float_as_uint(p3.x); al[i][3] = __float_as_uint(p3.y);
            }
#pragma unroll
            for (int j = 0; j < NT; j++) {
                int n = warp_n * (NT * 8) + j * 8 + gq;
                float2 q0 = Bs[(kk + tig)     * BNP + n];
                float2 q1 = Bs[(kk + tig + 4) * BNP + n];
                unsigned bh[2] = {__float_as_uint(q0.x), __float_as_uint(q1.x)};
                unsigned bl[2] = {__float_as_uint(q0.y), __float_as_uint(q1.y)};
#pragma unroll
                for (int i = 0; i < 2; i++) {
                    mma8(acc[i][j], ah[i], bh);
                    mma8(acc[i][j], ah[i], bl);
                    mma8(acc[i][j], al[i], bh);
                }
            }
        }
    }

#pragma unroll
    for (int i = 0; i < 2; i++) {
#pragma unroll
        for (int j = 0; j < NT; j++) {
            int row0 = blockRow + warp_m * 32 + i * 16 + gq;
            int col  = blockCol + warp_n * (NT * 8) + j * 8 + 2 * tig;
            if (row0 < M)
                *(float2*)&C[(size_t)row0 * N + col] = make_float2(acc[i][j][0], acc[i][j][1]);
            if (row0 + 8 < M)
                *(float2*)&C[(size_t)(row0 + 8) * N + col] = make_float2(acc[i][j][2], acc[i][j][3]);
        }
    }
}

// --------- layer-1 alphas + fused fp16 conversion of h1 ---------------------
__global__ void alphas1_kernel(const float* __restrict__ h,
                               const float* __restrict__ a_src,
                               const float* __restrict__ a_dst,
                               float* __restrict__ asrc,
                               float* __restrict__ adst,
                               __half* __restrict__ hh) {
    int i = blockIdx.x * blockDim.x + threadIdx.x;   // i = n*HEADS + head
    if (i >= NN * HEADS) return;
    int head = i & (HEADS - 1);
    size_t off = (size_t)(i >> 3) * HC1 + head * HID;
    const float4* hp = (const float4*)(h + off);
    const float4* s4 = (const float4*)(a_src + head * HID);
    const float4* d4 = (const float4*)(a_dst + head * HID);
    float s1 = 0.f, s2 = 0.f;
    __half2 o2[16];
#pragma unroll
    for (int c = 0; c < 8; c++) {
        float4 v = hp[c];
        float4 a = s4[c];
        float4 b = d4[c];
        s1 = fmaf(v.x, a.x, fmaf(v.y, a.y, fmaf(v.z, a.z, fmaf(v.w, a.w, s1))));
        s2 = fmaf(v.x, b.x, fmaf(v.y, b.y, fmaf(v.z, b.z, fmaf(v.w, b.w, s2))));
        o2[2 * c]     = __floats2half2_rn(v.x, v.y);
        o2[2 * c + 1] = __floats2half2_rn(v.z, v.w);
    }
    asrc[i] = s1;
    adst[i] = s2;
    uint4* dsth = (uint4*)(hh + off);
    const uint4* sv = (const uint4*)o2;
    dsth[0] = sv[0]; dsth[1] = sv[1]; dsth[2] = sv[2]; dsth[3] = sv[3];
}

// ---------------- layer-2 alphas --------------------------------------------
template<int C>
__global__ void alphas_kernel(const float* __restrict__ h,
                              const float* __restrict__ a_src,
                              const float* __restrict__ a_dst,
                              float* __restrict__ asrc,
                              float* __restrict__ adst) {
    int i = blockIdx.x * blockDim.x + threadIdx.x;
    if (i >= NN * HEADS) return;
    int hh = i & (HEADS - 1);
    const float4* hp = (const float4*)(h + (size_t)(i >> 3) * (HEADS * C) + hh * C);
    const float4* s4 = (const float4*)(a_src + hh * C);
    const float4* d4 = (const float4*)(a_dst + hh * C);
    float s1 = 0.f, s2 = 0.f;
#pragma unroll
    for (int c = 0; c < C / 4; c++) {
        float4 v = hp[c];
        float4 a = s4[c];
        float4 b = d4[c];
        s1 = fmaf(v.x, a.x, fmaf(v.y, a.y, fmaf(v.z, a.z, fmaf(v.w, a.w, s1))));
        s2 = fmaf(v.x, b.x, fmaf(v.y, b.y, fmaf(v.z, b.z, fmaf(v.w, b.w, s2))));
    }
    asrc[i] = s1;
    adst[i] = s2;
}

// ---------------- CSR construction ------------------------------------------
__global__ void count_kernel(const int* __restrict__ dst) {
    int e = blockIdx.x * blockDim.x + threadIdx.x;
    if (e < EE) atomicAdd(&g_counts[dst[e]], 1);
}

__global__ void scan_blocks_kernel() {
    __shared__ int sh[SCAN_B];
    int t = threadIdx.x;
    int i = blockIdx.x * SCAN_B + t;
    int v = (i < NN) ? (g_counts[i] + 1) : 0;   // +1 self loop
    sh[t] = v;
    __syncthreads();
    for (int off = 1; off < SCAN_B; off <<= 1) {
        int x = (t >= off) ? sh[t - off] : 0;
        __syncthreads();
        sh[t] += x;
        __syncthreads();
    }
    if (i < NN) g_rowptr[i + 1] = sh[t];
    if (t == SCAN_B - 1) g_blocksums[blockIdx.x] = sh[t];
}

__global__ void scan_finalize_kernel() {
    __shared__ int s_off;
    int t = threadIdx.x;
    int sb = (blockIdx.x * 256) / SCAN_B;
    if (t < 32) {
        int v = 0;
        if (t < sb) v += g_blocksums[t];
        if (t + 32 < sb) v += g_blocksums[t + 32];
#pragma unroll
        for (int off = 16; off > 0; off >>= 1)
            v += __shfl_down_sync(0xffffffffu, v, off);
        if (t == 0) s_off = v;
    }
    __syncthreads();
    int i = blockIdx.x * 256 + t;
    if (i == 0) g_rowptr[0] = 0;
    if (i < NN) {
        int e = g_rowptr[i + 1] + s_off;
        g_rowptr[i + 1] = e;
        int begin = e - (g_counts[i] + 1);
        g_csrsrc[begin] = i;        // self loop first
        g_counts[i] = begin + 1;    // scatter cursor
    }
}

__global__ void scatter_kernel(const int* __restrict__ src,
                               const int* __restrict__ dst) {
    int e = blockIdx.x * blockDim.x + threadIdx.x;
    if (e < EE) {
        int p = atomicAdd(&g_counts[dst[e]], 1);
        g_csrsrc[p] = src[e];
    }
}

// ---------------- aggregation: layer 1, warp per dst node, fp16 gather ------
// lane l owns cols [8l, 8l+8) => head hsel = l>>2. No shuffles: each quad
// redundantly computes its head's ex/denom. Gather = 1 uint4 (16B) per lane.
__global__ void agg1_kernel(const __half* __restrict__ hh,
                            const float* __restrict__ asrc,
                            const float* __restrict__ adst,
                            const float* __restrict__ bias,
                            float* __restrict__ out) {
    int warp = (blockIdx.x * blockDim.x + threadIdx.x) >> 5;
    int lane = threadIdx.x & 31;
    if (warp >= NN) return;

    int beg = g_rowptr[warp];
    int end = g_rowptr[warp + 1];
    int hsel = lane >> 2;

    float adst_l = adst[warp * HEADS + hsel];
    float tt = asrc[warp * HEADS + hsel] + adst_l;
    float aself = (tt > 0.f) ? tt : NEG * tt;   // self-loop logit = stabilizer

    float denom = 0.f;
    float acc[8];
#pragma unroll
    for (int r = 0; r < 8; r++) acc[r] = 0.f;

    for (int j = beg; j < end; j++) {
        int s = g_csrsrc[j];
        float a = asrc[s * HEADS + hsel] + adst_l;
        a = (a > 0.f) ? a : NEG * a;
        float ex = __expf(fminf(a - aself, 60.f));
        denom += ex;
        uint4 u = *((const uint4*)(hh + (size_t)s * HC1) + lane);
        float2 f0 = __half22float2(*(__half2*)&u.x);
        float2 f1 = __half22float2(*(__half2*)&u.y);
        float2 f2 = __half22float2(*(__half2*)&u.z);
        float2 f3 = __half22float2(*(__half2*)&u.w);
        acc[0] = fmaf(f0.x, ex, acc[0]); acc[1] = fmaf(f0.y, ex, acc[1]);
        acc[2] = fmaf(f1.x, ex, acc[2]); acc[3] = fmaf(f1.y, ex, acc[3]);
        acc[4] = fmaf(f2.x, ex, acc[4]); acc[5] = fmaf(f2.y, ex, acc[5]);
        acc[6] = fmaf(f3.x, ex, acc[6]); acc[7] = fmaf(f3.y, ex, acc[7]);
    }

    float d = denom + 1e-16f;
    const float4* b4 = (const float4*)bias + lane * 2;
    float4 bb0 = b4[0], bb1 = b4[1];
    float4 o0, o1;
    o0.x = acc[0] / d + bb0.x; o0.y = acc[1] / d + bb0.y;
    o0.z = acc[2] / d + bb0.z; o0.w = acc[3] / d + bb0.w;
    o1.x = acc[4] / d + bb1.x; o1.y = acc[5] / d + bb1.y;
    o1.z = acc[6] / d + bb1.z; o1.w = acc[7] / d + bb1.w;
    o0.x = (o0.x > 0.f) ? o0.x : NEG * o0.x; o0.y = (o0.y > 0.f) ? o0.y : NEG * o0.y;
    o0.z = (o0.z > 0.f) ? o0.z : NEG * o0.z; o0.w = (o0.w > 0.f) ? o0.w : NEG * o0.w;
    o1.x = (o1.x > 0.f) ? o1.x : NEG * o1.x; o1.y = (o1.y > 0.f) ? o1.y : NEG * o1.y;
    o1.z = (o1.z > 0.f) ? o1.z : NEG * o1.z; o1.w = (o1.w > 0.f) ? o1.w : NEG * o1.w;

    float4* op = (float4*)(out + (size_t)warp * HC1) + lane * 2;
    op[0] = o0;
    op[1] = o1;
}

// ---------------- aggregation: layer 2 (C=4), warp per dst node -------------
__global__ void agg2_kernel(const float* __restrict__ h,
                            const float* __restrict__ asrc,
                            const float* __restrict__ adst,
                            const float* __restrict__ bias,
                            float* __restrict__ out) {
    int warp = (blockIdx.x * blockDim.x + threadIdx.x) >> 5;
    int lane = threadIdx.x & 31;
    if (warp >= NN) return;

    int beg = g_rowptr[warp];
    int end = g_rowptr[warp + 1];
    int hh = lane >> 2;

    float as_d = asrc[warp * HEADS + hh];
    float adst_l = adst[warp * HEADS + hh];
    float tt = as_d + adst_l;
    float aself = (tt > 0.f) ? tt : NEG * tt;

    float denom_l = 0.f;
    float acc = 0.f;
    for (int j = beg; j < end; j++) {
        int s = g_csrsrc[j];
        float a = asrc[s * HEADS + hh] + adst_l;
        a = (a > 0.f) ? a : NEG * a;
        float ex = __expf(fminf(a - aself, 60.f));
        denom_l += ex;
        acc = fmaf(h[(size_t)s * HC2 + lane], ex, acc);
    }

    out[(size_t)warp * HC2 + lane] = acc / (denom_l + 1e-16f) + bias[lane];
}

// ---------------- launch ------------------------------------------------------
extern "C" void kernel_launch(void* const* d_in, const int* in_sizes, int n_in,
                              void* d_out, int out_size) {
    const float* x      = (const float*)d_in[0];
    const int*   ei     = (const int*)d_in[1];
    const float* W1     = (const float*)d_in[2];
    const float* a_src1 = (const float*)d_in[3];
    const float* a_dst1 = (const float*)d_in[4];
    const float* b1     = (const float*)d_in[5];
    const float* W2     = (const float*)d_in[6];
    const float* a_src2 = (const float*)d_in[7];
    const float* a_dst2 = (const float*)d_in[8];
    const float* b2     = (const float*)d_in[9];
    float* out = (float*)d_out;

    const int* src = ei;
    const int* dst = ei + EE;

    float *h1, *o1, *h2, *as1, *ad1, *as2, *ad2;
    __half *h1h;
    int *cnts;
    cudaGetSymbolAddress((void**)&h1,  g_h1);
    cudaGetSymbolAddress((void**)&h1h, g_h1h);
    cudaGetSymbolAddress((void**)&o1,  g_o1);
    cudaGetSymbolAddress((void**)&h2,  g_h2);
    cudaGetSymbolAddress((void**)&as1, g_asrc1);
    cudaGetSymbolAddress((void**)&ad1, g_adst1);
    cudaGetSymbolAddress((void**)&as2, g_asrc2);
    cudaGetSymbolAddress((void**)&ad2, g_adst2);
    cudaGetSymbolAddress((void**)&cnts, g_counts);

    const int smem1 = (128 * 36 + 32 * 132) * (int)sizeof(float2);  // 70656
    const int smem2sz = (128 * 36 + 32 * 36) * (int)sizeof(float2); // 46080
    cudaFuncSetAttribute(gemm_tf32_kernel<128>,
                         cudaFuncAttributeMaxDynamicSharedMemorySize, smem1);
    cudaFuncSetAttribute(gemm_tf32_kernel<32>,
                         cudaFuncAttributeMaxDynamicSharedMemorySize, smem2sz);

    static cudaStream_t s2 = nullptr;
    static cudaEvent_t evFork = nullptr, evJoin = nullptr;
    if (s2 == nullptr) {
        cudaStreamCreateWithFlags(&s2, cudaStreamNonBlocking);
        cudaEventCreateWithFlags(&evFork, cudaEventDisableTiming);
        cudaEventCreateWithFlags(&evJoin, cudaEventDisableTiming);
    }

    // --- fork: CSR build on s2, GEMM1 chain on main stream -------------------
    cudaEventRecord(evFork, 0);
    cudaStreamWaitEvent(s2, evFork, 0);

    cudaMemsetAsync(cnts, 0, NN * sizeof(int), s2);
    count_kernel<<<(EE + 255) / 256, 256, 0, s2>>>(dst);
    scan_blocks_kernel<<<NBLK, SCAN_B, 0, s2>>>();
    scan_finalize_kernel<<<(NN + 255) / 256, 256, 0, s2>>>();
    scatter_kernel<<<(EE + 255) / 256, 256, 0, s2>>>(src, dst);
    cudaEventRecord(evJoin, s2);

    // main stream: GEMM1 + alphas1(+fp16 conv)
    {
        dim3 grid(HC1 / 128, (NN + 127) / 128);
        gemm_tf32_kernel<128><<<grid, 256, smem1>>>(NN, HC1, FIN, x, W1, h1);
    }
    alphas1_kernel<<<(NN * HEADS + 255) / 256, 256>>>(h1, a_src1, a_dst1, as1, ad1, h1h);

    // --- join: agg1 needs both branches --------------------------------------
    cudaStreamWaitEvent(0, evJoin, 0);
    agg1_kernel<<<(NN * 32 + 255) / 256, 256>>>(h1h, as1, ad1, b1, o1);

    // --- layer 2 ---
    {
        dim3 grid(1, (NN + 127) / 128);
        gemm_tf32_kernel<32><<<grid, 256, smem2sz>>>(NN, HC2, HC1, o1, W2, h2);
    }
    alphas_kernel<OUTC><<<(NN * HEADS + 255) / 256, 256>>>(h2, a_src2, a_dst2, as2, ad2);
    agg2_kernel<<<(NN * 32 + 255) / 256, 256>>>(h2, as2, ad2, b2, out);
}

// round 9
// speedup vs baseline: 1.9504x; 1.1830x over previous
#include <cuda_runtime.h>
#include <cuda_fp16.h>
#include <math.h>

// Problem constants (fixed shapes)
#define NN   50000
#define EE   800000
#define FIN  128
#define HEADS 8
#define HID  32
#define OUTC 4
#define HC1  (HEADS*HID)   // 256
#define HC2  (HEADS*OUTC)  // 32
#define NEG  0.2f

#define SCAN_B 1024
#define NBLK   ((NN + SCAN_B - 1) / SCAN_B)   // 49

// ---------------- scratch (__device__ globals; no runtime allocation) -------
__device__ __half g_h1h[NN * HC1];      // fp16 h1 (only copy)
__device__ float  g_o1[NN * HC1];
__device__ __half g_h2h[NN * HC2];      // fp16 h2 (only copy)
__device__ float  g_asrc1[NN * HEADS], g_adst1[NN * HEADS];
__device__ float  g_asrc2[NN * HEADS], g_adst2[NN * HEADS];
__device__ int    g_rowptr[NN + 1];
__device__ int    g_counts[NN];         // histogram, then scatter cursor
__device__ int    g_csrsrc[EE + NN];
__device__ int    g_blocksums[NBLK + 1];

// ---------------- tf32 helpers ----------------------------------------------
__device__ __forceinline__ float tf32r(float v) {
    float r;
    asm("cvt.rna.tf32.f32 %0, %1;" : "=f"(r) : "f"(v));
    return r;
}
__device__ __forceinline__ void mma8(float* c, const unsigned* a, const unsigned* b) {
    asm volatile(
        "mma.sync.aligned.m16n8k8.row.col.f32.tf32.tf32.f32 "
        "{%0,%1,%2,%3}, {%4,%5,%6,%7}, {%8,%9}, {%0,%1,%2,%3};\n"
        : "+f"(c[0]), "+f"(c[1]), "+f"(c[2]), "+f"(c[3])
        : "r"(a[0]), "r"(a[1]), "r"(a[2]), "r"(a[3]), "r"(b[0]), "r"(b[1]));
}

// ===== GEMM1 (3xTF32) fused with alphas1 + fp16 output ======================
// M=NN, N=256, K=128. grid(2, ceil(M/128)), 256 thr. Block x covers heads
// 4x..4x+3. Output: h1h (fp16) + asrc1/adst1.
__global__ __launch_bounds__(256, 2)
void gemm1_fused_kernel(int M,
                        const float* __restrict__ A,
                        const float* __restrict__ B,
                        const float* __restrict__ a_src,
                        const float* __restrict__ a_dst,
                        __half* __restrict__ Ch,
                        float* __restrict__ asrc,
                        float* __restrict__ adst) {
    constexpr int BM = 128, BK = 32, BN = 128, K = FIN, N = HC1;
    constexpr int NT  = BN / 16;      // 8
    constexpr int BKP = 36;
    constexpr int BNP = BN + 4;       // 132
    constexpr int BNV = BN / 4;
    constexpr int BLD = (BK * BNV) / 256;

    extern __shared__ float2 smem2[];
    float2* As = smem2;               // [BM][BKP]
    float2* Bs = smem2 + BM * BKP;    // [BK][BNP]

    const int tid = threadIdx.x;
    const int wid = tid >> 5, lane = tid & 31;
    const int gq = lane >> 2, tig = lane & 3;
    const int warp_m = wid & 3, warp_n = wid >> 2;
    const int blockRow = blockIdx.y * BM;
    const int blockCol = blockIdx.x * BN;

    float acc[2][NT][4];
#pragma unroll
    for (int i = 0; i < 2; i++)
#pragma unroll
        for (int j = 0; j < NT; j++)
#pragma unroll
            for (int r = 0; r < 4; r++) acc[i][j][r] = 0.f;

    for (int k0 = 0; k0 < K; k0 += BK) {
        if (k0) __syncthreads();
#pragma unroll
        for (int l = 0; l < 4; l++) {
            int idx = tid + l * 256;
            int m = idx >> 3, kv = idx & 7;
            int gm = blockRow + m;
            float4 v = (gm < M) ? *(const float4*)&A[(size_t)gm * K + k0 + kv * 4]
                                : make_float4(0.f, 0.f, 0.f, 0.f);
            float hx = tf32r(v.x), hy = tf32r(v.y), hz = tf32r(v.z), hw = tf32r(v.w);
            As[m * BKP + kv * 4 + 0] = make_float2(hx, tf32r(v.x - hx));
            As[m * BKP + kv * 4 + 1] = make_float2(hy, tf32r(v.y - hy));
            As[m * BKP + kv * 4 + 2] = make_float2(hz, tf32r(v.z - hz));
            As[m * BKP + kv * 4 + 3] = make_float2(hw, tf32r(v.w - hw));
        }
#pragma unroll
        for (int l = 0; l < BLD; l++) {
            int idx = tid + l * 256;
            int k = idx / BNV, nv = idx % BNV;
            float4 v = *(const float4*)&B[(size_t)(k0 + k) * N + blockCol + nv * 4];
            float hx = tf32r(v.x), hy = tf32r(v.y), hz = tf32r(v.z), hw = tf32r(v.w);
            Bs[k * BNP + nv * 4 + 0] = make_float2(hx, tf32r(v.x - hx));
            Bs[k * BNP + nv * 4 + 1] = make_float2(hy, tf32r(v.y - hy));
            Bs[k * BNP + nv * 4 + 2] = make_float2(hz, tf32r(v.z - hz));
            Bs[k * BNP + nv * 4 + 3] = make_float2(hw, tf32r(v.w - hw));
        }
        __syncthreads();

#pragma unroll
        for (int ks = 0; ks < BK / 8; ks++) {
            const int kk = ks * 8;
            unsigned ah[2][4], al[2][4];
#pragma unroll
            for (int i = 0; i < 2; i++) {
                int m0 = warp_m * 32 + i * 16 + gq;
                float2 p0 = As[(m0)     * BKP + kk + tig];
                float2 p1 = As[(m0 + 8) * BKP + kk + tig];
                float2 p2 = As[(m0)     * BKP + kk + tig + 4];
                float2 p3 = As[(m0 + 8) * BKP + kk + tig + 4];
                ah[i][0] = __float_as_uint(p0.x); al[i][0] = __float_as_uint(p0.y);
                ah[i][1] = __float_as_uint(p1.x); al[i][1] = __float_as_uint(p1.y);
                ah[i][2] = __float_as_uint(p2.x); al[i][2] = __float_as_uint(p2.y);
                ah[i][3] = __float_as_uint(p3.x); al[i][3] = __float_as_uint(p3.y);
            }
#pragma unroll
            for (int j = 0; j < NT; j++) {
                int n = warp_n * (NT * 8) + j * 8 + gq;
                float2 q0 = Bs[(kk + tig)     * BNP + n];
                float2 q1 = Bs[(kk + tig + 4) * BNP + n];
                unsigned bh[2] = {__float_as_uint(q0.x), __float_as_uint(q1.x)};
                unsigned bl[2] = {__float_as_uint(q0.y), __float_as_uint(q1.y)};
#pragma unroll
                for (int i = 0; i < 2; i++) {
                    mma8(acc[i][j], ah[i], bh);
                    mma8(acc[i][j], ah[i], bl);
                    mma8(acc[i][j], al[i], bh);
                }
            }
        }
    }

    // ---- fused epilogue: fp16 store + per-head alpha partials --------------
    // thread's cols: gcol(j,c) = blockCol + warp_n*64 + j*8 + 2*tig + c
    // head(j) = (blockCol>>5) + warp_n*2 + (j>>2); lcol(j,c) = (j&3)*8 + 2*tig + c
    float s1[2][2][2], s2[2][2][2];   // [i][rr][g]
#pragma unroll
    for (int i = 0; i < 2; i++)
#pragma unroll
        for (int rr = 0; rr < 2; rr++)
#pragma unroll
            for (int g = 0; g < 2; g++) { s1[i][rr][g] = 0.f; s2[i][rr][g] = 0.f; }

    const int headBase = (blockCol >> 5) + warp_n * 2;

#pragma unroll
    for (int j = 0; j < NT; j++) {
        int g = j >> 2;
        int head = headBase + g;
        int lc = (j & 3) * 8 + 2 * tig;
        float2 wsrc = *(const float2*)&a_src[head * HID + lc];
        float2 wdst = *(const float2*)&a_dst[head * HID + lc];
#pragma unroll
        for (int i = 0; i < 2; i++) {
            s1[i][0][g] += acc[i][j][0] * wsrc.x + acc[i][j][1] * wsrc.y;
            s1[i][1][g] += acc[i][j][2] * wsrc.x + acc[i][j][3] * wsrc.y;
            s2[i][0][g] += acc[i][j][0] * wdst.x + acc[i][j][1] * wdst.y;
            s2[i][1][g] += acc[i][j][2] * wdst.x + acc[i][j][3] * wdst.y;
        }
        // fp16 stores (2 rows per i)
        int coloff = blockCol + warp_n * 64 + j * 8 + 2 * tig;
#pragma unroll
        for (int i = 0; i < 2; i++) {
            int row0 = blockRow + warp_m * 32 + i * 16 + gq;
            if (row0 < M)
                *(__half2*)&Ch[(size_t)row0 * N + coloff] =
                    __floats2half2_rn(acc[i][j][0], acc[i][j][1]);
            if (row0 + 8 < M)
                *(__half2*)&Ch[(size_t)(row0 + 8) * N + coloff] =
                    __floats2half2_rn(acc[i][j][2], acc[i][j][3]);
        }
    }

    // quad reduction over tig (lanes gq*4+tig; xor bits 0,1 stay in quad)
#pragma unroll
    for (int i = 0; i < 2; i++)
#pragma unroll
        for (int rr = 0; rr < 2; rr++)
#pragma unroll
            for (int g = 0; g < 2; g++) {
                float v1 = s1[i][rr][g], v2 = s2[i][rr][g];
                v1 += __shfl_xor_sync(0xffffffffu, v1, 1);
                v1 += __shfl_xor_sync(0xffffffffu, v1, 2);
                v2 += __shfl_xor_sync(0xffffffffu, v2, 1);
                v2 += __shfl_xor_sync(0xffffffffu, v2, 2);
                if (tig == 0) {
                    int row = blockRow + warp_m * 32 + i * 16 + gq + rr * 8;
                    if (row < M) {
                        asrc[row * HEADS + headBase + g] = v1;
                        adst[row * HEADS + headBase + g] = v2;
                    }
                }
            }
}

// ===== GEMM2 (3xTF32) fused with alphas2 + fp16 output ======================
// M=NN, N=32, K=256. grid(1, ceil(M/128)). head = 4 cols.
__global__ __launch_bounds__(256, 2)
void gemm2_fused_kernel(int M,
                        const float* __restrict__ A,
                        const float* __restrict__ B,
                        const float* __restrict__ a_src,
                        const float* __restrict__ a_dst,
                        __half* __restrict__ Ch,
                        float* __restrict__ asrc,
                        float* __restrict__ adst) {
    constexpr int BM = 128, BK = 32, BN = 32, K = HC1, N = HC2;
    constexpr int NT  = BN / 16;      // 2
    constexpr int BKP = 36;
    constexpr int BNP = BN + 4;       // 36
    constexpr int BNV = BN / 4;
    constexpr int BLD = (BK * BNV) / 256;

    extern __shared__ float2 smem2[];
    float2* As = smem2;
    float2* Bs = smem2 + BM * BKP;

    const int tid = threadIdx.x;
    const int wid = tid >> 5, lane = tid & 31;
    const int gq = lane >> 2, tig = lane & 3;
    const int warp_m = wid & 3, warp_n = wid >> 2;
    const int blockRow = blockIdx.y * BM;

    float acc[2][NT][4];
#pragma unroll
    for (int i = 0; i < 2; i++)
#pragma unroll
        for (int j = 0; j < NT; j++)
#pragma unroll
            for (int r = 0; r < 4; r++) acc[i][j][r] = 0.f;

    for (int k0 = 0; k0 < K; k0 += BK) {
        if (k0) __syncthreads();
#pragma unroll
        for (int l = 0; l < 4; l++) {
            int idx = tid + l * 256;
            int m = idx >> 3, kv = idx & 7;
            int gm = blockRow + m;
            float4 v = (gm < M) ? *(const float4*)&A[(size_t)gm * K + k0 + kv * 4]
                                : make_float4(0.f, 0.f, 0.f, 0.f);
            float hx = tf32r(v.x), hy = tf32r(v.y), hz = tf32r(v.z), hw = tf32r(v.w);
            As[m * BKP + kv * 4 + 0] = make_float2(hx, tf32r(v.x - hx));
            As[m * BKP + kv * 4 + 1] = make_float2(hy, tf32r(v.y - hy));
            As[m * BKP + kv * 4 + 2] = make_float2(hz, tf32r(v.z - hz));
            As[m * BKP + kv * 4 + 3] = make_float2(hw, tf32r(v.w - hw));
        }
#pragma unroll
        for (int l = 0; l < BLD; l++) {
            int idx = tid + l * 256;
            int k = idx / BNV, nv = idx % BNV;
            float4 v = *(const float4*)&B[(size_t)(k0 + k) * N + nv * 4];
            float hx = tf32r(v.x), hy = tf32r(v.y), hz = tf32r(v.z), hw = tf32r(v.w);
            Bs[k * BNP + nv * 4 + 0] = make_float2(hx, tf32r(v.x - hx));
            Bs[k * BNP + nv * 4 + 1] = make_float2(hy, tf32r(v.y - hy));
            Bs[k * BNP + nv * 4 + 2] = make_float2(hz, tf32r(v.z - hz));
            Bs[k * BNP + nv * 4 + 3] = make_float2(hw, tf32r(v.w - hw));
        }
        __syncthreads();

#pragma unroll
        for (int ks = 0; ks < BK / 8; ks++) {
            const int kk = ks * 8;
            unsigned ah[2][4], al[2][4];
#pragma unroll
            for (int i = 0; i < 2; i++) {
                int m0 = warp_m * 32 + i * 16 + gq;
                float2 p0 = As[(m0)     * BKP + kk + tig];
                float2 p1 = As[(m0 + 8) * BKP + kk + tig];
                float2 p2 = As[(m0)     * BKP + kk + tig + 4];
                float2 p3 = As[(m0 + 8) * BKP + kk + tig + 4];
                ah[i][0] = __float_as_uint(p0.x); al[i][0] = __float_as_uint(p0.y);
                ah[i][1] = __float_as_uint(p1.x); al[i][1] = __float_as_uint(p1.y);
                ah[i][2] = __float_as_uint(p2.x); al[i][2] = __float_as_uint(p2.y);
                ah[i][3] = __float_as_uint(p3.x); al[i][3] = __float_as_uint(p3.y);
            }
#pragma unroll
            for (int j = 0; j < NT; j++) {
                int n = warp_n * (NT * 8) + j * 8 + gq;
                float2 q0 = Bs[(kk + tig)     * BNP + n];
                float2 q1 = Bs[(kk + tig + 4) * BNP + n];
                unsigned bh[2] = {__float_as_uint(q0.x), __float_as_uint(q1.x)};
                unsigned bl[2] = {__float_as_uint(q0.y), __float_as_uint(q1.y)};
#pragma unroll
                for (int i = 0; i < 2; i++) {
                    mma8(acc[i][j], ah[i], bh);
                    mma8(acc[i][j], ah[i], bl);
                    mma8(acc[i][j], al[i], bh);
                }
            }
        }
    }

    // ---- fused epilogue --------------------------------------------------
    // col(j,c) = warp_n*16 + j*8 + 2*tig + c; head = warp_n*4 + 2j + (tig>>1)
    // lcol = 2*(tig&1) + c
#pragma unroll
    for (int j = 0; j < NT; j++) {
        int head = warp_n * 4 + 2 * j + (tig >> 1);
        float2 wsrc = *(const float2*)&a_src[head * OUTC + 2 * (tig & 1)];
        float2 wdst = *(const float2*)&a_dst[head * OUTC + 2 * (tig & 1)];
        int coloff = warp_n * 16 + j * 8 + 2 * tig;
#pragma unroll
        for (int i = 0; i < 2; i++) {
#pragma unroll
            for (int rr = 0; rr < 2; rr++) {
                float p1 = acc[i][j][2 * rr] * wsrc.x + acc[i][j][2 * rr + 1] * wsrc.y;
                float p2 = acc[i][j][2 * rr] * wdst.x + acc[i][j][2 * rr + 1] * wdst.y;
                p1 += __shfl_xor_sync(0xffffffffu, p1, 1);
                p2 += __shfl_xor_sync(0xffffffffu, p2, 1);
                int row = blockRow + warp_m * 32 + i * 16 + gq + rr * 8;
                if ((tig & 1) == 0 && row < M) {
                    asrc[row * HEADS + head] = p1;
                    adst[row * HEADS + head] = p2;
                }
            }
            int row0 = blockRow + warp_m * 32 + i * 16 + gq;
            if (row0 < M)
                *(__half2*)&Ch[(size_t)row0 * N + coloff] =
                    __floats2half2_rn(acc[i][j][0], acc[i][j][1]);
            if (row0 + 8 < M)
                *(__half2*)&Ch[(size_t)(row0 + 8) * N + coloff] =
                    __floats2half2_rn(acc[i][j][2], acc[i][j][3]);
        }
    }
}

// ---------------- CSR construction ------------------------------------------
__global__ void count_kernel(const int* __restrict__ dst) {
    int e = blockIdx.x * blockDim.x + threadIdx.x;
    if (e < EE) atomicAdd(&g_counts[dst[e]], 1);
}

__global__ void scan_blocks_kernel() {
    __shared__ int sh[SCAN_B];
    int t = threadIdx.x;
    int i = blockIdx.x * SCAN_B + t;
    int v = (i < NN) ? (g_counts[i] + 1) : 0;   // +1 self loop
    sh[t] = v;
    __syncthreads();
    for (int off = 1; off < SCAN_B; off <<= 1) {
        int x = (t >= off) ? sh[t - off] : 0;
        __syncthreads();
        sh[t] += x;
        __syncthreads();
    }
    if (i < NN) g_rowptr[i + 1] = sh[t];
    if (t == SCAN_B - 1) g_blocksums[blockIdx.x] = sh[t];
}

__global__ void scan_finalize_kernel() {
    __shared__ int s_off;
    int t = threadIdx.x;
    int sb = (blockIdx.x * 256) / SCAN_B;
    if (t < 32) {
        int v = 0;
        if (t < sb) v += g_blocksums[t];
        if (t + 32 < sb) v += g_blocksums[t + 32];
#pragma unroll
        for (int off = 16; off > 0; off >>= 1)
            v += __shfl_down_sync(0xffffffffu, v, off);
        if (t == 0) s_off = v;
    }
    __syncthreads();
    int i = blockIdx.x * 256 + t;
    if (i == 0) g_rowptr[0] = 0;
    if (i < NN) {
        int e = g_rowptr[i + 1] + s_off;
        g_rowptr[i + 1] = e;
        int begin = e - (g_counts[i] + 1);
        g_csrsrc[begin] = i;        // self loop first
        g_counts[i] = begin + 1;    // scatter cursor
    }
}

__global__ void scatter_kernel(const int* __restrict__ src,
                               const int* __restrict__ dst) {
    int e = blockIdx.x * blockDim.x + threadIdx.x;
    if (e < EE) {
        int p = atomicAdd(&g_counts[dst[e]], 1);
        g_csrsrc[p] = src[e];
    }
}

// ---------------- aggregation: layer 1, warp per dst node, fp16 gather ------
__global__ void agg1_kernel(const __half* __restrict__ hh,
                            const float* __restrict__ asrc,
                            const float* __restrict__ adst,
                            const float* __restrict__ bias,
                            float* __restrict__ out) {
    int warp = (blockIdx.x * blockDim.x + threadIdx.x) >> 5;
    int lane = threadIdx.x & 31;
    if (warp >= NN) return;

    int beg = g_rowptr[warp];
    int end = g_rowptr[warp + 1];
    int hsel = lane >> 2;

    float adst_l = adst[warp * HEADS + hsel];
    float tt = asrc[warp * HEADS + hsel] + adst_l;
    float aself = (tt > 0.f) ? tt : NEG * tt;   // self-loop logit = stabilizer

    float denom = 0.f;
    float acc[8];
#pragma unroll
    for (int r = 0; r < 8; r++) acc[r] = 0.f;

    for (int j = beg; j < end; j++) {
        int s = g_csrsrc[j];
        float a = asrc[s * HEADS + hsel] + adst_l;
        a = (a > 0.f) ? a : NEG * a;
        float ex = __expf(fminf(a - aself, 60.f));
        denom += ex;
        uint4 u = *((const uint4*)(hh + (size_t)s * HC1) + lane);
        float2 f0 = __half22float2(*(__half2*)&u.x);
        float2 f1 = __half22float2(*(__half2*)&u.y);
        float2 f2 = __half22float2(*(__half2*)&u.z);
        float2 f3 = __half22float2(*(__half2*)&u.w);
        acc[0] = fmaf(f0.x, ex, acc[0]); acc[1] = fmaf(f0.y, ex, acc[1]);
        acc[2] = fmaf(f1.x, ex, acc[2]); acc[3] = fmaf(f1.y, ex, acc[3]);
        acc[4] = fmaf(f2.x, ex, acc[4]); acc[5] = fmaf(f2.y, ex, acc[5]);
        acc[6] = fmaf(f3.x, ex, acc[6]); acc[7] = fmaf(f3.y, ex, acc[7]);
    }

    float d = denom + 1e-16f;
    const float4* b4 = (const float4*)bias + lane * 2;
    float4 bb0 = b4[0], bb1 = b4[1];
    float4 o0, o1;
    o0.x = acc[0] / d + bb0.x; o0.y = acc[1] / d + bb0.y;
    o0.z = acc[2] / d + bb0.z; o0.w = acc[3] / d + bb0.w;
    o1.x = acc[4] / d + bb1.x; o1.y = acc[5] / d + bb1.y;
    o1.z = acc[6] / d + bb1.z; o1.w = acc[7] / d + bb1.w;
    o0.x = (o0.x > 0.f) ? o0.x : NEG * o0.x; o0.y = (o0.y > 0.f) ? o0.y : NEG * o0.y;
    o0.z = (o0.z > 0.f) ? o0.z : NEG * o0.z; o0.w = (o0.w > 0.f) ? o0.w : NEG * o0.w;
    o1.x = (o1.x > 0.f) ? o1.x : NEG * o1.x; o1.y = (o1.y > 0.f) ? o1.y : NEG * o1.y;
    o1.z = (o1.z > 0.f) ? o1.z : NEG * o1.z; o1.w = (o1.w > 0.f) ? o1.w : NEG * o1.w;

    float4* op = (float4*)(out + (size_t)warp * HC1) + lane * 2;
    op[0] = o0;
    op[1] = o1;
}

// ---------------- aggregation: layer 2 (C=4), fp16 gather -------------------
__global__ void agg2_kernel(const __half* __restrict__ hh,
                            const float* __restrict__ asrc,
                            const float* __restrict__ adst,
                            const float* __restrict__ bias,
                            float* __restrict__ out) {
    int warp = (blockIdx.x * blockDim.x + threadIdx.x) >> 5;
    int lane = threadIdx.x & 31;
    if (warp >= NN) return;

    int beg = g_rowptr[warp];
    int end = g_rowptr[warp + 1];
    int hd = lane >> 2;

    float adst_l = adst[warp * HEADS + hd];
    float tt = asrc[warp * HEADS + hd] + adst_l;
    float aself = (tt > 0.f) ? tt : NEG * tt;

    float denom_l = 0.f;
    float acc = 0.f;
    for (int j = beg; j < end; j++) {
        int s = g_csrsrc[j];
        float a = asrc[s * HEADS + hd] + adst_l;
        a = (a > 0.f) ? a : NEG * a;
        float ex = __expf(fminf(a - aself, 60.f));
        denom_l += ex;
        float v = __half2float(hh[(size_t)s * HC2 + lane]);
        acc = fmaf(v, ex, acc);
    }

    out[(size_t)warp * HC2 + lane] = acc / (denom_l + 1e-16f) + bias[lane];
}

// ---------------- launch ------------------------------------------------------
extern "C" void kernel_launch(void* const* d_in, const int* in_sizes, int n_in,
                              void* d_out, int out_size) {
    const float* x      = (const float*)d_in[0];
    const int*   ei     = (const int*)d_in[1];
    const float* W1     = (const float*)d_in[2];
    const float* a_src1 = (const float*)d_in[3];
    const float* a_dst1 = (const float*)d_in[4];
    const float* b1     = (const float*)d_in[5];
    const float* W2     = (const float*)d_in[6];
    const float* a_src2 = (const float*)d_in[7];
    const float* a_dst2 = (const float*)d_in[8];
    const float* b2     = (const float*)d_in[9];
    float* out = (float*)d_out;

    const int* src = ei;
    const int* dst = ei + EE;

    float *o1, *as1, *ad1, *as2, *ad2;
    __half *h1h, *h2h;
    int *cnts;
    cudaGetSymbolAddress((void**)&h1h, g_h1h);
    cudaGetSymbolAddress((void**)&o1,  g_o1);
    cudaGetSymbolAddress((void**)&h2h, g_h2h);
    cudaGetSymbolAddress((void**)&as1, g_asrc1);
    cudaGetSymbolAddress((void**)&ad1, g_adst1);
    cudaGetSymbolAddress((void**)&as2, g_asrc2);
    cudaGetSymbolAddress((void**)&ad2, g_adst2);
    cudaGetSymbolAddress((void**)&cnts, g_counts);

    const int smem1 = (128 * 36 + 32 * 132) * (int)sizeof(float2);  // 70656
    const int smem2sz = (128 * 36 + 32 * 36) * (int)sizeof(float2); // 46080
    cudaFuncSetAttribute(gemm1_fused_kernel,
                         cudaFuncAttributeMaxDynamicSharedMemorySize, smem1);
    cudaFuncSetAttribute(gemm2_fused_kernel,
                         cudaFuncAttributeMaxDynamicSharedMemorySize, smem2sz);

    static cudaStream_t s2 = nullptr;
    static cudaEvent_t evFork = nullptr, evJoin = nullptr;
    if (s2 == nullptr) {
        cudaStreamCreateWithFlags(&s2, cudaStreamNonBlocking);
        cudaEventCreateWithFlags(&evFork, cudaEventDisableTiming);
        cudaEventCreateWithFlags(&evJoin, cudaEventDisableTiming);
    }

    // --- fork: CSR build on s2, GEMM1 on main stream -------------------------
    cudaEventRecord(evFork, 0);
    cudaStreamWaitEvent(s2, evFork, 0);

    cudaMemsetAsync(cnts, 0, NN * sizeof(int), s2);
    count_kernel<<<(EE + 255) / 256, 256, 0, s2>>>(dst);
    scan_blocks_kernel<<<NBLK, SCAN_B, 0, s2>>>();
    scan_finalize_kernel<<<(NN + 255) / 256, 256, 0, s2>>>();
    scatter_kernel<<<(EE + 255) / 256, 256, 0, s2>>>(src, dst);
    cudaEventRecord(evJoin, s2);

    // main stream: GEMM1 (fused alphas + fp16)
    {
        dim3 grid(2, (NN + 127) / 128);
        gemm1_fused_kernel<<<grid, 256, smem1>>>(NN, x, W1, a_src1, a_dst1,
                                                 h1h, as1, ad1);
    }

    // --- join: agg1 needs both branches --------------------------------------
    cudaStreamWaitEvent(0, evJoin, 0);
    agg1_kernel<<<(NN * 32 + 255) / 256, 256>>>(h1h, as1, ad1, b1, o1);

    // --- layer 2 ---
    {
        dim3 grid(1, (NN + 127) / 128);
        gemm2_fused_kernel<<<grid, 256, smem2sz>>>(NN, o1, W2, a_src2, a_dst2,
                                                   h2h, as2, ad2);
    }
    agg2_kernel<<<(NN * 32 + 255) / 256, 256>>>(h2h, as2, ad2, b2, out);
}

// round 10
// speedup vs baseline: 2.1046x; 1.0791x over previous
#include <cuda_runtime.h>
#include <cuda_fp16.h>
#include <math.h>

// Problem constants (fixed shapes)
#define NN   50000
#define EE   800000
#define FIN  128
#define HEADS 8
#define HID  32
#define OUTC 4
#define HC1  (HEADS*HID)   // 256
#define HC2  (HEADS*OUTC)  // 32
#define NEG  0.2f

#define SCAN_B 1024
#define NBLK   ((NN + SCAN_B - 1) / SCAN_B)   // 49
#define NH0   25088                           // half-split boundary (196*128)

// ---------------- scratch (__device__ globals; no runtime allocation) -------
__device__ __half g_h1h[NN * HC1];      // fp16 h1
__device__ __half g_o1h[NN * HC1];      // fp16 o1 (agg1 output)
__device__ __half g_h2h[NN * HC2];      // fp16 h2
__device__ float  g_asrc1[NN * HEADS], g_adst1[NN * HEADS];
__device__ float  g_asrc2[NN * HEADS], g_adst2[NN * HEADS];
__device__ int    g_rowptr[NN + 1];
__device__ int    g_counts[NN];
__device__ int    g_csrsrc[EE + NN];
__device__ int    g_blocksums[NBLK + 1];

// ---------------- mma helpers ------------------------------------------------
__device__ __forceinline__ float tf32r(float v) {
    float r;
    asm("cvt.rna.tf32.f32 %0, %1;" : "=f"(r) : "f"(v));
    return r;
}
__device__ __forceinline__ void mma8(float* c, const unsigned* a, const unsigned* b) {
    asm volatile(
        "mma.sync.aligned.m16n8k8.row.col.f32.tf32.tf32.f32 "
        "{%0,%1,%2,%3}, {%4,%5,%6,%7}, {%8,%9}, {%0,%1,%2,%3};\n"
        : "+f"(c[0]), "+f"(c[1]), "+f"(c[2]), "+f"(c[3])
        : "r"(a[0]), "r"(a[1]), "r"(a[2]), "r"(a[3]), "r"(b[0]), "r"(b[1]));
}
__device__ __forceinline__ void mma16h(float* c, const unsigned* a, const unsigned* b) {
    asm volatile(
        "mma.sync.aligned.m16n8k16.row.col.f32.f16.f16.f32 "
        "{%0,%1,%2,%3}, {%4,%5,%6,%7}, {%8,%9}, {%0,%1,%2,%3};\n"
        : "+f"(c[0]), "+f"(c[1]), "+f"(c[2]), "+f"(c[3])
        : "r"(a[0]), "r"(a[1]), "r"(a[2]), "r"(a[3]), "r"(b[0]), "r"(b[1]));
}

// ===== GEMM1 (3xTF32) fused with alphas1 + fp16 output ======================
__global__ __launch_bounds__(256, 2)
void gemm1_fused_kernel(int M,
                        const float* __restrict__ A,
                        const float* __restrict__ B,
                        const float* __restrict__ a_src,
                        const float* __restrict__ a_dst,
                        __half* __restrict__ Ch,
                        float* __restrict__ asrc,
                        float* __restrict__ adst) {
    constexpr int BM = 128, BK = 32, BN = 128, K = FIN, N = HC1;
    constexpr int NT  = BN / 16;      // 8
    constexpr int BKP = 36;
    constexpr int BNP = BN + 4;       // 132
    constexpr int BNV = BN / 4;
    constexpr int BLD = (BK * BNV) / 256;

    extern __shared__ float2 smem2[];
    float2* As = smem2;               // [BM][BKP]
    float2* Bs = smem2 + BM * BKP;    // [BK][BNP]

    const int tid = threadIdx.x;
    const int wid = tid >> 5, lane = tid & 31;
    const int gq = lane >> 2, tig = lane & 3;
    const int warp_m = wid & 3, warp_n = wid >> 2;
    const int blockRow = blockIdx.y * BM;
    const int blockCol = blockIdx.x * BN;

    float acc[2][NT][4];
#pragma unroll
    for (int i = 0; i < 2; i++)
#pragma unroll
        for (int j = 0; j < NT; j++)
#pragma unroll
            for (int r = 0; r < 4; r++) acc[i][j][r] = 0.f;

    for (int k0 = 0; k0 < K; k0 += BK) {
        if (k0) __syncthreads();
#pragma unroll
        for (int l = 0; l < 4; l++) {
            int idx = tid + l * 256;
            int m = idx >> 3, kv = idx & 7;
            int gm = blockRow + m;
            float4 v = (gm < M) ? *(const float4*)&A[(size_t)gm * K + k0 + kv * 4]
                                : make_float4(0.f, 0.f, 0.f, 0.f);
            float hx = tf32r(v.x), hy = tf32r(v.y), hz = tf32r(v.z), hw = tf32r(v.w);
            As[m * BKP + kv * 4 + 0] = make_float2(hx, tf32r(v.x - hx));
            As[m * BKP + kv * 4 + 1] = make_float2(hy, tf32r(v.y - hy));
            As[m * BKP + kv * 4 + 2] = make_float2(hz, tf32r(v.z - hz));
            As[m * BKP + kv * 4 + 3] = make_float2(hw, tf32r(v.w - hw));
        }
#pragma unroll
        for (int l = 0; l < BLD; l++) {
            int idx = tid + l * 256;
            int k = idx / BNV, nv = idx % BNV;
            float4 v = *(const float4*)&B[(size_t)(k0 + k) * N + blockCol + nv * 4];
            float hx = tf32r(v.x), hy = tf32r(v.y), hz = tf32r(v.z), hw = tf32r(v.w);
            Bs[k * BNP + nv * 4 + 0] = make_float2(hx, tf32r(v.x - hx));
            Bs[k * BNP + nv * 4 + 1] = make_float2(hy, tf32r(v.y - hy));
            Bs[k * BNP + nv * 4 + 2] = make_float2(hz, tf32r(v.z - hz));
            Bs[k * BNP + nv * 4 + 3] = make_float2(hw, tf32r(v.w - hw));
        }
        __syncthreads();

#pragma unroll
        for (int ks = 0; ks < BK / 8; ks++) {
            const int kk = ks * 8;
            unsigned ah[2][4], al[2][4];
#pragma unroll
            for (int i = 0; i < 2; i++) {
                int m0 = warp_m * 32 + i * 16 + gq;
                float2 p0 = As[(m0)     * BKP + kk + tig];
                float2 p1 = As[(m0 + 8) * BKP + kk + tig];
                float2 p2 = As[(m0)     * BKP + kk + tig + 4];
                float2 p3 = As[(m0 + 8) * BKP + kk + tig + 4];
                ah[i][0] = __float_as_uint(p0.x); al[i][0] = __float_as_uint(p0.y);
                ah[i][1] = __float_as_uint(p1.x); al[i][1] = __float_as_uint(p1.y);
                ah[i][2] = __float_as_uint(p2.x); al[i][2] = __float_as_uint(p2.y);
                ah[i][3] = __float_as_uint(p3.x); al[i][3] = __float_as_uint(p3.y);
            }
#pragma unroll
            for (int j = 0; j < NT; j++) {
                int n = warp_n * (NT * 8) + j * 8 + gq;
                float2 q0 = Bs[(kk + tig)     * BNP + n];
                float2 q1 = Bs[(kk + tig + 4) * BNP + n];
                unsigned bh[2] = {__float_as_uint(q0.x), __float_as_uint(q1.x)};
                unsigned bl[2] = {__float_as_uint(q0.y), __float_as_uint(q1.y)};
#pragma unroll
                for (int i = 0; i < 2; i++) {
                    mma8(acc[i][j], ah[i], bh);
                    mma8(acc[i][j], ah[i], bl);
                    mma8(acc[i][j], al[i], bh);
                }
            }
        }
    }

    // ---- fused epilogue: fp16 store + per-head alpha partials --------------
    float s1[2][2][2], s2[2][2][2];
#pragma unroll
    for (int i = 0; i < 2; i++)
#pragma unroll
        for (int rr = 0; rr < 2; rr++)
#pragma unroll
            for (int g = 0; g < 2; g++) { s1[i][rr][g] = 0.f; s2[i][rr][g] = 0.f; }

    const int headBase = (blockCol >> 5) + warp_n * 2;

#pragma unroll
    for (int j = 0; j < NT; j++) {
        int g = j >> 2;
        int head = headBase + g;
        int lc = (j & 3) * 8 + 2 * tig;
        float2 wsrc = *(const float2*)&a_src[head * HID + lc];
        float2 wdst = *(const float2*)&a_dst[head * HID + lc];
#pragma unroll
        for (int i = 0; i < 2; i++) {
            s1[i][0][g] += acc[i][j][0] * wsrc.x + acc[i][j][1] * wsrc.y;
            s1[i][1][g] += acc[i][j][2] * wsrc.x + acc[i][j][3] * wsrc.y;
            s2[i][0][g] += acc[i][j][0] * wdst.x + acc[i][j][1] * wdst.y;
            s2[i][1][g] += acc[i][j][2] * wdst.x + acc[i][j][3] * wdst.y;
        }
        int coloff = blockCol + warp_n * 64 + j * 8 + 2 * tig;
#pragma unroll
        for (int i = 0; i < 2; i++) {
            int row0 = blockRow + warp_m * 32 + i * 16 + gq;
            if (row0 < M)
                *(__half2*)&Ch[(size_t)row0 * N + coloff] =
                    __floats2half2_rn(acc[i][j][0], acc[i][j][1]);
            if (row0 + 8 < M)
                *(__half2*)&Ch[(size_t)(row0 + 8) * N + coloff] =
                    __floats2half2_rn(acc[i][j][2], acc[i][j][3]);
        }
    }

#pragma unroll
    for (int i = 0; i < 2; i++)
#pragma unroll
        for (int rr = 0; rr < 2; rr++)
#pragma unroll
            for (int g = 0; g < 2; g++) {
                float v1 = s1[i][rr][g], v2 = s2[i][rr][g];
                v1 += __shfl_xor_sync(0xffffffffu, v1, 1);
                v1 += __shfl_xor_sync(0xffffffffu, v1, 2);
                v2 += __shfl_xor_sync(0xffffffffu, v2, 1);
                v2 += __shfl_xor_sync(0xffffffffu, v2, 2);
                if (tig == 0) {
                    int row = blockRow + warp_m * 32 + i * 16 + gq + rr * 8;
                    if (row < M) {
                        asrc[row * HEADS + headBase + g] = v1;
                        adst[row * HEADS + headBase + g] = v2;
                    }
                }
            }
}

// ===== GEMM2 (fp16 mma) fused with alphas2 + fp16 output ====================
// A = o1 (fp16, exact pass-through), B = W2 converted to fp16 in staging.
// M rows processed: blockRow = rowBase + by*128, guarded by M.
__global__ __launch_bounds__(256)
void gemm2_fp16_kernel(int rowBase, int M,
                       const __half* __restrict__ Ah,
                       const float* __restrict__ B,
                       const float* __restrict__ a_src,
                       const float* __restrict__ a_dst,
                       __half* __restrict__ Ch,
                       float* __restrict__ asrc,
                       float* __restrict__ adst) {
    constexpr int BK = 32, K = HC1, N = HC2;
    constexpr int NT = 2;
    constexpr int AP = 18;            // A row pitch in half2 (conflict-free)

    __shared__ unsigned As2[128 * AP];      // half2-packed A tile
    __shared__ __half  Bs[32][40];

    const int tid = threadIdx.x;
    const int wid = tid >> 5, lane = tid & 31;
    const int gq = lane >> 2, tig = lane & 3;
    const int warp_m = wid & 3, warp_n = wid >> 2;
    const int blockRow = rowBase + blockIdx.y * 128;

    float acc[2][NT][4];
#pragma unroll
    for (int i = 0; i < 2; i++)
#pragma unroll
        for (int j = 0; j < NT; j++)
#pragma unroll
            for (int r = 0; r < 4; r++) acc[i][j][r] = 0.f;

    for (int k0 = 0; k0 < K; k0 += BK) {
        if (k0) __syncthreads();
        // stage A: 128x32 fp16, 2 uint4 per thread
#pragma unroll
        for (int l = 0; l < 2; l++) {
            int idx = tid + l * 256;
            int m = idx >> 2, seg = idx & 3;
            int gm = blockRow + m;
            uint4 u = make_uint4(0u, 0u, 0u, 0u);
            if (gm < M) u = *(const uint4*)&Ah[(size_t)gm * K + k0 + seg * 8];
            As2[m * AP + seg * 4 + 0] = u.x;
            As2[m * AP + seg * 4 + 1] = u.y;
            As2[m * AP + seg * 4 + 2] = u.z;
            As2[m * AP + seg * 4 + 3] = u.w;
        }
        // stage B: 32x32 fp32 -> fp16, one float4 per thread
        {
            int k = tid >> 3, n4 = tid & 7;
            float4 v = *(const float4*)&B[(size_t)(k0 + k) * N + n4 * 4];
            Bs[k][n4 * 4 + 0] = __float2half_rn(v.x);
            Bs[k][n4 * 4 + 1] = __float2half_rn(v.y);
            Bs[k][n4 * 4 + 2] = __float2half_rn(v.z);
            Bs[k][n4 * 4 + 3] = __float2half_rn(v.w);
        }
        __syncthreads();

#pragma unroll
        for (int ks = 0; ks < 2; ks++) {
            const int kh2 = ks * 8;    // half2 offset
            const int kk = ks * 16;    // half offset
            unsigned a[2][4];
#pragma unroll
            for (int i = 0; i < 2; i++) {
                int m0 = warp_m * 32 + i * 16 + gq;
                a[i][0] = As2[(m0)     * AP + kh2 + tig];
                a[i][1] = As2[(m0 + 8) * AP + kh2 + tig];
                a[i][2] = As2[(m0)     * AP + kh2 + 4 + tig];
                a[i][3] = As2[(m0 + 8) * AP + kh2 + 4 + tig];
            }
#pragma unroll
            for (int j = 0; j < NT; j++) {
                int n = warp_n * 16 + j * 8 + gq;
                __half2 hb0 = __halves2half2(Bs[kk + 2 * tig][n], Bs[kk + 2 * tig + 1][n]);
                __half2 hb1 = __halves2half2(Bs[kk + 2 * tig + 8][n], Bs[kk + 2 * tig + 9][n]);
                unsigned b[2] = {*(unsigned*)&hb0, *(unsigned*)&hb1};
#pragma unroll
                for (int i = 0; i < 2; i++)
                    mma16h(acc[i][j], a[i], b);
            }
        }
    }

    // ---- fused epilogue ----------------------------------------------------
#pragma unroll
    for (int j = 0; j < NT; j++) {
        int head = warp_n * 4 + 2 * j + (tig >> 1);
        float2 wsrc = *(const float2*)&a_src[head * OUTC + 2 * (tig & 1)];
        float2 wdst = *(const float2*)&a_dst[head * OUTC + 2 * (tig & 1)];
        int coloff = warp_n * 16 + j * 8 + 2 * tig;
#pragma unroll
        for (int i = 0; i < 2; i++) {
#pragma unroll
            for (int rr = 0; rr < 2; rr++) {
                float p1 = acc[i][j][2 * rr] * wsrc.x + acc[i][j][2 * rr + 1] * wsrc.y;
                float p2 = acc[i][j][2 * rr] * wdst.x + acc[i][j][2 * rr + 1] * wdst.y;
                p1 += __shfl_xor_sync(0xffffffffu, p1, 1);
                p2 += __shfl_xor_sync(0xffffffffu, p2, 1);
                int row = blockRow + warp_m * 32 + i * 16 + gq + rr * 8;
                if ((tig & 1) == 0 && row < M) {
                    asrc[row * HEADS + head] = p1;
                    adst[row * HEADS + head] = p2;
                }
            }
            int row0 = blockRow + warp_m * 32 + i * 16 + gq;
            if (row0 < M)
                *(__half2*)&Ch[(size_t)row0 * N + coloff] =
                    __floats2half2_rn(acc[i][j][0], acc[i][j][1]);
            if (row0 + 8 < M)
                *(__half2*)&Ch[(size_t)(row0 + 8) * N + coloff] =
                    __floats2half2_rn(acc[i][j][2], acc[i][j][3]);
        }
    }
}

// ---------------- CSR construction ------------------------------------------
__global__ void count_kernel(const int* __restrict__ dst) {
    int e = blockIdx.x * blockDim.x + threadIdx.x;
    if (e < EE) atomicAdd(&g_counts[dst[e]], 1);
}

__global__ void scan_blocks_kernel() {
    __shared__ int sh[SCAN_B];
    int t = threadIdx.x;
    int i = blockIdx.x * SCAN_B + t;
    int v = (i < NN) ? (g_counts[i] + 1) : 0;   // +1 self loop
    sh[t] = v;
    __syncthreads();
    for (int off = 1; off < SCAN_B; off <<= 1) {
        int x = (t >= off) ? sh[t - off] : 0;
        __syncthreads();
        sh[t] += x;
        __syncthreads();
    }
    if (i < NN) g_rowptr[i + 1] = sh[t];
    if (t == SCAN_B - 1) g_blocksums[blockIdx.x] = sh[t];
}

__global__ void scan_finalize_kernel() {
    __shared__ int s_off;
    int t = threadIdx.x;
    int sb = (blockIdx.x * 256) / SCAN_B;
    if (t < 32) {
        int v = 0;
        if (t < sb) v += g_blocksums[t];
        if (t + 32 < sb) v += g_blocksums[t + 32];
#pragma unroll
        for (int off = 16; off > 0; off >>= 1)
            v += __shfl_down_sync(0xffffffffu, v, off);
        if (t == 0) s_off = v;
    }
    __syncthreads();
    int i = blockIdx.x * 256 + t;
    if (i == 0) g_rowptr[0] = 0;
    if (i < NN) {
        int e = g_rowptr[i + 1] + s_off;
        g_rowptr[i + 1] = e;
        int begin = e - (g_counts[i] + 1);
        g_csrsrc[begin] = i;        // self loop first
        g_counts[i] = begin + 1;    // scatter cursor
    }
}

__global__ void scatter_kernel(const int* __restrict__ src,
                               const int* __restrict__ dst) {
    int e = blockIdx.x * blockDim.x + threadIdx.x;
    if (e < EE) {
        int p = atomicAdd(&g_counts[dst[e]], 1);
        g_csrsrc[p] = src[e];
    }
}

// ---------------- aggregation: layer 1, warp per dst node, fp16 I/O ---------
__global__ void agg1_kernel(const __half* __restrict__ hh,
                            const float* __restrict__ asrc,
                            const float* __restrict__ adst,
                            const float* __restrict__ bias,
                            __half* __restrict__ outh,
                            int nodeBase, int nodeEnd) {
    int node = nodeBase + ((blockIdx.x * blockDim.x + threadIdx.x) >> 5);
    int lane = threadIdx.x & 31;
    if (node >= nodeEnd) return;

    int beg = g_rowptr[node];
    int end = g_rowptr[node + 1];
    int hsel = lane >> 2;

    float adst_l = adst[node * HEADS + hsel];
    float tt = asrc[node * HEADS + hsel] + adst_l;
    float aself = (tt > 0.f) ? tt : NEG * tt;   // self-loop logit = stabilizer

    float denom = 0.f;
    float acc[8];
#pragma unroll
    for (int r = 0; r < 8; r++) acc[r] = 0.f;

    int j = beg;
    for (; j + 1 < end; j += 2) {
        int s0 = g_csrsrc[j];
        int s1v = g_csrsrc[j + 1];
        float a0 = asrc[s0 * HEADS + hsel] + adst_l;
        float a1 = asrc[s1v * HEADS + hsel] + adst_l;
        uint4 u0 = *((const uint4*)(hh + (size_t)s0 * HC1) + lane);
        uint4 u1 = *((const uint4*)(hh + (size_t)s1v * HC1) + lane);
        a0 = (a0 > 0.f) ? a0 : NEG * a0;
        a1 = (a1 > 0.f) ? a1 : NEG * a1;
        float ex0 = __expf(fminf(a0 - aself, 60.f));
        float ex1 = __expf(fminf(a1 - aself, 60.f));
        denom += ex0 + ex1;
        float2 f;
        f = __half22float2(*(__half2*)&u0.x); acc[0] = fmaf(f.x, ex0, acc[0]); acc[1] = fmaf(f.y, ex0, acc[1]);
        f = __half22float2(*(__half2*)&u0.y); acc[2] = fmaf(f.x, ex0, acc[2]); acc[3] = fmaf(f.y, ex0, acc[3]);
        f = __half22float2(*(__half2*)&u0.z); acc[4] = fmaf(f.x, ex0, acc[4]); acc[5] = fmaf(f.y, ex0, acc[5]);
        f = __half22float2(*(__half2*)&u0.w); acc[6] = fmaf(f.x, ex0, acc[6]); acc[7] = fmaf(f.y, ex0, acc[7]);
        f = __half22float2(*(__half2*)&u1.x); acc[0] = fmaf(f.x, ex1, acc[0]); acc[1] = fmaf(f.y, ex1, acc[1]);
        f = __half22float2(*(__half2*)&u1.y); acc[2] = fmaf(f.x, ex1, acc[2]); acc[3] = fmaf(f.y, ex1, acc[3]);
        f = __half22float2(*(__half2*)&u1.z); acc[4] = fmaf(f.x, ex1, acc[4]); acc[5] = fmaf(f.y, ex1, acc[5]);
        f = __half22float2(*(__half2*)&u1.w); acc[6] = fmaf(f.x, ex1, acc[6]); acc[7] = fmaf(f.y, ex1, acc[7]);
    }
    if (j < end) {
        int s = g_csrsrc[j];
        float a = asrc[s * HEADS + hsel] + adst_l;
        a = (a > 0.f) ? a : NEG * a;
        float ex = __expf(fminf(a - aself, 60.f));
        denom += ex;
        uint4 u = *((const uint4*)(hh + (size_t)s * HC1) + lane);
        float2 f;
        f = __half22float2(*(__half2*)&u.x); acc[0] = fmaf(f.x, ex, acc[0]); acc[1] = fmaf(f.y, ex, acc[1]);
        f = __half22float2(*(__half2*)&u.y); acc[2] = fmaf(f.x, ex, acc[2]); acc[3] = fmaf(f.y, ex, acc[3]);
        f = __half22float2(*(__half2*)&u.z); acc[4] = fmaf(f.x, ex, acc[4]); acc[5] = fmaf(f.y, ex, acc[5]);
        f = __half22float2(*(__half2*)&u.w); acc[6] = fmaf(f.x, ex, acc[6]); acc[7] = fmaf(f.y, ex, acc[7]);
    }

    float d = denom + 1e-16f;
    const float4* b4 = (const float4*)bias + lane * 2;
    float4 bb0 = b4[0], bb1 = b4[1];
    float o[8];
    o[0] = acc[0] / d + bb0.x; o[1] = acc[1] / d + bb0.y;
    o[2] = acc[2] / d + bb0.z; o[3] = acc[3] / d + bb0.w;
    o[4] = acc[4] / d + bb1.x; o[5] = acc[5] / d + bb1.y;
    o[6] = acc[6] / d + bb1.z; o[7] = acc[7] / d + bb1.w;
#pragma unroll
    for (int r = 0; r < 8; r++) o[r] = (o[r] > 0.f) ? o[r] : NEG * o[r];

    __half2 ho[4];
    ho[0] = __floats2half2_rn(o[0], o[1]);
    ho[1] = __floats2half2_rn(o[2], o[3]);
    ho[2] = __floats2half2_rn(o[4], o[5]);
    ho[3] = __floats2half2_rn(o[6], o[7]);
    *(uint4*)(outh + (size_t)node * HC1 + lane * 8) = *(uint4*)ho;
}

// ---------------- aggregation: layer 2 (C=4), fp16 gather -------------------
__global__ void agg2_kernel(const __half* __restrict__ hh,
                            const float* __restrict__ asrc,
                            const float* __restrict__ adst,
                            const float* __restrict__ bias,
                            float* __restrict__ out) {
    int warp = (blockIdx.x * blockDim.x + threadIdx.x) >> 5;
    int lane = threadIdx.x & 31;
    if (warp >= NN) return;

    int beg = g_rowptr[warp];
    int end = g_rowptr[warp + 1];
    int hd = lane >> 2;

    float adst_l = adst[warp * HEADS + hd];
    float tt = asrc[warp * HEADS + hd] + adst_l;
    float aself = (tt > 0.f) ? tt : NEG * tt;

    float denom = 0.f;
    float acc = 0.f;
    int j = beg;
    for (; j + 1 < end; j += 2) {
        int s0 = g_csrsrc[j];
        int s1v = g_csrsrc[j + 1];
        float a0 = asrc[s0 * HEADS + hd] + adst_l;
        float a1 = asrc[s1v * HEADS + hd] + adst_l;
        float v0 = __half2float(hh[(size_t)s0 * HC2 + lane]);
        float v1 = __half2float(hh[(size_t)s1v * HC2 + lane]);
        a0 = (a0 > 0.f) ? a0 : NEG * a0;
        a1 = (a1 > 0.f) ? a1 : NEG * a1;
        float ex0 = __expf(fminf(a0 - aself, 60.f));
        float ex1 = __expf(fminf(a1 - aself, 60.f));
        denom += ex0 + ex1;
        acc = fmaf(v0, ex0, acc);
        acc = fmaf(v1, ex1, acc);
    }
    if (j < end) {
        int s = g_csrsrc[j];
        float a = asrc[s * HEADS + hd] + adst_l;
        a = (a > 0.f) ? a : NEG * a;
        float ex = __expf(fminf(a - aself, 60.f));
        denom += ex;
        acc = fmaf(__half2float(hh[(size_t)s * HC2 + lane]), ex, acc);
    }

    out[(size_t)warp * HC2 + lane] = acc / (denom + 1e-16f) + bias[lane];
}

// ---------------- launch ------------------------------------------------------
extern "C" void kernel_launch(void* const* d_in, const int* in_sizes, int n_in,
                              void* d_out, int out_size) {
    const float* x      = (const float*)d_in[0];
    const int*   ei     = (const int*)d_in[1];
    const float* W1     = (const float*)d_in[2];
    const float* a_src1 = (const float*)d_in[3];
    const float* a_dst1 = (const float*)d_in[4];
    const float* b1     = (const float*)d_in[5];
    const float* W2     = (const float*)d_in[6];
    const float* a_src2 = (const float*)d_in[7];
    const float* a_dst2 = (const float*)d_in[8];
    const float* b2     = (const float*)d_in[9];
    float* out = (float*)d_out;

    const int* src = ei;
    const int* dst = ei + EE;

    float *as1, *ad1, *as2, *ad2;
    __half *h1h, *o1h, *h2h;
    int *cnts;
    cudaGetSymbolAddress((void**)&h1h, g_h1h);
    cudaGetSymbolAddress((void**)&o1h, g_o1h);
    cudaGetSymbolAddress((void**)&h2h, g_h2h);
    cudaGetSymbolAddress((void**)&as1, g_asrc1);
    cudaGetSymbolAddress((void**)&ad1, g_adst1);
    cudaGetSymbolAddress((void**)&as2, g_asrc2);
    cudaGetSymbolAddress((void**)&ad2, g_adst2);
    cudaGetSymbolAddress((void**)&cnts, g_counts);

    const int smem1 = (128 * 36 + 32 * 132) * (int)sizeof(float2);  // 70656
    cudaFuncSetAttribute(gemm1_fused_kernel,
                         cudaFuncAttributeMaxDynamicSharedMemorySize, smem1);

    static cudaStream_t s2 = nullptr;
    static cudaEvent_t evFork = nullptr, evJoin = nullptr, evA = nullptr, evB = nullptr;
    if (s2 == nullptr) {
        cudaStreamCreateWithFlags(&s2, cudaStreamNonBlocking);
        cudaEventCreateWithFlags(&evFork, cudaEventDisableTiming);
        cudaEventCreateWithFlags(&evJoin, cudaEventDisableTiming);
        cudaEventCreateWithFlags(&evA, cudaEventDisableTiming);
        cudaEventCreateWithFlags(&evB, cudaEventDisableTiming);
    }

    // --- fork: CSR build on s2, GEMM1 on main stream -------------------------
    cudaEventRecord(evFork, 0);
    cudaStreamWaitEvent(s2, evFork, 0);

    cudaMemsetAsync(cnts, 0, NN * sizeof(int), s2);
    count_kernel<<<(EE + 255) / 256, 256, 0, s2>>>(dst);
    scan_blocks_kernel<<<NBLK, SCAN_B, 0, s2>>>();
    scan_finalize_kernel<<<(NN + 255) / 256, 256, 0, s2>>>();
    scatter_kernel<<<(EE + 255) / 256, 256, 0, s2>>>(src, dst);
    cudaEventRecord(evJoin, s2);

    // main stream: GEMM1 (fused alphas + fp16)
    {
        dim3 grid(2, (NN + 127) / 128);
        gemm1_fused_kernel<<<grid, 256, smem1>>>(NN, x, W1, a_src1, a_dst1,
                                                 h1h, as1, ad1);
    }

    // --- join, then half-split agg1 / gemm2 pipeline --------------------------
    cudaStreamWaitEvent(0, evJoin, 0);
    agg1_kernel<<<(NH0 * 32 + 255) / 256, 256>>>(h1h, as1, ad1, b1, o1h, 0, NH0);
    cudaEventRecord(evA, 0);
    agg1_kernel<<<((NN - NH0) * 32 + 255) / 256, 256>>>(h1h, as1, ad1, b1, o1h, NH0, NN);

    // side stream: gemm2 on first half (overlaps agg1 second half)
    cudaStreamWaitEvent(s2, evA, 0);
    {
        dim3 grid(1, NH0 / 128);
        gemm2_fp16_kernel<<<grid, 256, 0, s2>>>(0, NN, o1h, W2, a_src2, a_dst2,
                                                h2h, as2, ad2);
    }
    cudaEventRecord(evB, s2);

    // main stream: gemm2 on second half
    {
        dim3 grid(1, (NN - NH0 + 127) / 128);
        gemm2_fp16_kernel<<<grid, 256>>>(NH0, NN, o1h, W2, a_src2, a_dst2,
                                         h2h, as2, ad2);
    }

    // --- join both gemm2 halves, then agg2 -----------------------------------
    cudaStreamWaitEvent(0, evB, 0);
    agg2_kernel<<<(NN * 32 + 255) / 256, 256>>>(h2h, as2, ad2, b2, out);
}

// round 11
// speedup vs baseline: 2.5033x; 1.1894x over previous
#include <cuda_runtime.h>
#include <cuda_fp16.h>
#include <math.h>

// Problem constants (fixed shapes)
#define NN   50000
#define EE   800000
#define FIN  128
#define HEADS 8
#define HID  32
#define OUTC 4
#define HC1  (HEADS*HID)   // 256
#define HC2  (HEADS*OUTC)  // 32
#define NEG  0.2f

#define SCAN_B 1024
#define NBLK   ((NN + SCAN_B - 1) / SCAN_B)   // 49
#define NH0   25088                           // half-split boundary (196*128)

// ---------------- scratch (__device__ globals; no runtime allocation) -------
__device__ __half g_h1h[NN * HC1];      // fp16 h1
__device__ __half g_o1h[NN * HC1];      // fp16 o1 (agg1 output)
__device__ __half g_h2h[NN * HC2];      // fp16 h2
__device__ float  g_asrc1[NN * HEADS], g_adst1[NN * HEADS];
__device__ float  g_asrc2[NN * HEADS], g_adst2[NN * HEADS];
__device__ int    g_rowptr[NN + 1];
__device__ int    g_counts[NN];
__device__ int    g_rank[EE];
__device__ int    g_csrsrc[EE + NN];
__device__ int    g_blocksums[NBLK + 1];

// ---------------- mma helper -------------------------------------------------
__device__ __forceinline__ void mma16h(float* c, const unsigned* a, const unsigned* b) {
    asm volatile(
        "mma.sync.aligned.m16n8k16.row.col.f32.f16.f16.f32 "
        "{%0,%1,%2,%3}, {%4,%5,%6,%7}, {%8,%9}, {%0,%1,%2,%3};\n"
        : "+f"(c[0]), "+f"(c[1]), "+f"(c[2]), "+f"(c[3])
        : "r"(a[0]), "r"(a[1]), "r"(a[2]), "r"(a[3]), "r"(b[0]), "r"(b[1]));
}
__device__ __forceinline__ unsigned h2pack(float a, float b) {
    __half2 h = __floats2half2_rn(a, b);
    return *(unsigned*)&h;
}

// ===== GEMM1 (3x fp16-split mma) fused with alphas1 + fp16 output ===========
// C = A@B via hi*hi + hi*lo + lo*hi (Ootomo split, fp32-class accuracy).
// M=NN, N=256, K=128. grid(2, ceil(M/128)), 256 thr.
__global__ __launch_bounds__(256, 2)
void gemm1_fused_kernel(int M,
                        const float* __restrict__ A,
                        const float* __restrict__ B,
                        const float* __restrict__ a_src,
                        const float* __restrict__ a_dst,
                        __half* __restrict__ Ch,
                        float* __restrict__ asrc,
                        float* __restrict__ adst) {
    constexpr int BK = 32, K = FIN, N = HC1;
    constexpr int NT = 8;             // n8-tiles per warp (BN=128, 2 n-warps)
    constexpr int AP = 18;            // A plane pitch (half2): 16 + 2 pad
    constexpr int BP = 132;           // B plane pitch (half2 over k-pairs): 128 + 4

    __shared__ unsigned Ah_s[128 * AP], Al_s[128 * AP];   // 9216 B each
    __shared__ unsigned Bh_s[16 * BP],  Bl_s[16 * BP];    // 8448 B each

    const int tid = threadIdx.x;
    const int wid = tid >> 5, lane = tid & 31;
    const int gq = lane >> 2, tig = lane & 3;
    const int warp_m = wid & 3, warp_n = wid >> 2;
    const int blockRow = blockIdx.y * 128;
    const int blockCol = blockIdx.x * 128;

    float acc[2][NT][4];
#pragma unroll
    for (int i = 0; i < 2; i++)
#pragma unroll
        for (int j = 0; j < NT; j++)
#pragma unroll
            for (int r = 0; r < 4; r++) acc[i][j][r] = 0.f;

    for (int k0 = 0; k0 < K; k0 += BK) {
        if (k0) __syncthreads();
        // stage A: 128x32 fp32 -> hi/lo fp16 planes, half2-packed along k
#pragma unroll
        for (int l = 0; l < 4; l++) {
            int idx = tid + l * 256;
            int m = idx >> 3, kv = idx & 7;          // kv: float4 index (k = kv*4)
            int gm = blockRow + m;
            float4 v = (gm < M) ? *(const float4*)&A[(size_t)gm * K + k0 + kv * 4]
                                : make_float4(0.f, 0.f, 0.f, 0.f);
            __half hx = __float2half_rn(v.x), hy = __float2half_rn(v.y);
            __half hz = __float2half_rn(v.z), hw = __float2half_rn(v.w);
            float lx = v.x - __half2float(hx), ly = v.y - __half2float(hy);
            float lz = v.z - __half2float(hz), lw = v.w - __half2float(hw);
            __half2 hh0 = __halves2half2(hx, hy), hh1 = __halves2half2(hz, hw);
            Ah_s[m * AP + kv * 2 + 0] = *(unsigned*)&hh0;
            Ah_s[m * AP + kv * 2 + 1] = *(unsigned*)&hh1;
            Al_s[m * AP + kv * 2 + 0] = h2pack(lx, ly);
            Al_s[m * AP + kv * 2 + 1] = h2pack(lz, lw);
        }
        // stage B: 32x128 fp32 -> hi/lo planes, half2 paired ACROSS k
#pragma unroll
        for (int l = 0; l < 2; l++) {
            int idx = tid + l * 256;
            int k2 = idx >> 5, n4 = idx & 31;        // k pair (2k2, 2k2+1), n = n4*4
            const float* r0 = &B[(size_t)(k0 + 2 * k2) * N + blockCol + n4 * 4];
            const float* r1 = r0 + N;
            float4 v = *(const float4*)r0;
            float4 w = *(const float4*)r1;
            float va[4] = {v.x, v.y, v.z, v.w};
            float wa[4] = {w.x, w.y, w.z, w.w};
#pragma unroll
            for (int c = 0; c < 4; c++) {
                __half h0 = __float2half_rn(va[c]), h1 = __float2half_rn(wa[c]);
                __half2 hp = __halves2half2(h0, h1);
                Bh_s[k2 * BP + n4 * 4 + c] = *(unsigned*)&hp;
                Bl_s[k2 * BP + n4 * 4 + c] =
                    h2pack(va[c] - __half2float(h0), wa[c] - __half2float(h1));
            }
        }
        __syncthreads();

#pragma unroll
        for (int ks = 0; ks < 2; ks++) {
            const int kh2 = ks * 8;
            unsigned ah[2][4], al[2][4];
#pragma unroll
            for (int i = 0; i < 2; i++) {
                int m0 = warp_m * 32 + i * 16 + gq;
                ah[i][0] = Ah_s[(m0)     * AP + kh2 + tig];
                ah[i][1] = Ah_s[(m0 + 8) * AP + kh2 + tig];
                ah[i][2] = Ah_s[(m0)     * AP + kh2 + 4 + tig];
                ah[i][3] = Ah_s[(m0 + 8) * AP + kh2 + 4 + tig];
                al[i][0] = Al_s[(m0)     * AP + kh2 + tig];
                al[i][1] = Al_s[(m0 + 8) * AP + kh2 + tig];
                al[i][2] = Al_s[(m0)     * AP + kh2 + 4 + tig];
                al[i][3] = Al_s[(m0 + 8) * AP + kh2 + 4 + tig];
            }
#pragma unroll
            for (int j = 0; j < NT; j++) {
                int n = warp_n * 64 + j * 8 + gq;
                unsigned bh[2], bl[2];
                bh[0] = Bh_s[(kh2 + tig)     * BP + n];
                bh[1] = Bh_s[(kh2 + 4 + tig) * BP + n];
                bl[0] = Bl_s[(kh2 + tig)     * BP + n];
                bl[1] = Bl_s[(kh2 + 4 + tig) * BP + n];
#pragma unroll
                for (int i = 0; i < 2; i++) {
                    mma16h(acc[i][j], ah[i], bh);
                    mma16h(acc[i][j], ah[i], bl);
                    mma16h(acc[i][j], al[i], bh);
                }
            }
        }
    }

    // ---- fused epilogue: fp16 store + per-head alpha partials --------------
    float s1[2][2][2], s2[2][2][2];
#pragma unroll
    for (int i = 0; i < 2; i++)
#pragma unroll
        for (int rr = 0; rr < 2; rr++)
#pragma unroll
            for (int g = 0; g < 2; g++) { s1[i][rr][g] = 0.f; s2[i][rr][g] = 0.f; }

    const int headBase = (blockCol >> 5) + warp_n * 2;

#pragma unroll
    for (int j = 0; j < NT; j++) {
        int g = j >> 2;
        int head = headBase + g;
        int lc = (j & 3) * 8 + 2 * tig;
        float2 wsrc = *(const float2*)&a_src[head * HID + lc];
        float2 wdst = *(const float2*)&a_dst[head * HID + lc];
#pragma unroll
        for (int i = 0; i < 2; i++) {
            s1[i][0][g] += acc[i][j][0] * wsrc.x + acc[i][j][1] * wsrc.y;
            s1[i][1][g] += acc[i][j][2] * wsrc.x + acc[i][j][3] * wsrc.y;
            s2[i][0][g] += acc[i][j][0] * wdst.x + acc[i][j][1] * wdst.y;
            s2[i][1][g] += acc[i][j][2] * wdst.x + acc[i][j][3] * wdst.y;
        }
        int coloff = blockCol + warp_n * 64 + j * 8 + 2 * tig;
#pragma unroll
        for (int i = 0; i < 2; i++) {
            int row0 = blockRow + warp_m * 32 + i * 16 + gq;
            if (row0 < M)
                *(__half2*)&Ch[(size_t)row0 * HC1 + coloff] =
                    __floats2half2_rn(acc[i][j][0], acc[i][j][1]);
            if (row0 + 8 < M)
                *(__half2*)&Ch[(size_t)(row0 + 8) * HC1 + coloff] =
                    __floats2half2_rn(acc[i][j][2], acc[i][j][3]);
        }
    }

#pragma unroll
    for (int i = 0; i < 2; i++)
#pragma unroll
        for (int rr = 0; rr < 2; rr++)
#pragma unroll
            for (int g = 0; g < 2; g++) {
                float v1 = s1[i][rr][g], v2 = s2[i][rr][g];
                v1 += __shfl_xor_sync(0xffffffffu, v1, 1);
                v1 += __shfl_xor_sync(0xffffffffu, v1, 2);
                v2 += __shfl_xor_sync(0xffffffffu, v2, 1);
                v2 += __shfl_xor_sync(0xffffffffu, v2, 2);
                if (tig == 0) {
                    int row = blockRow + warp_m * 32 + i * 16 + gq + rr * 8;
                    if (row < M) {
                        asrc[row * HEADS + headBase + g] = v1;
                        adst[row * HEADS + headBase + g] = v2;
                    }
                }
            }
}

// ===== GEMM2 (fp16 mma) fused with alphas2 + fp16 output ====================
__global__ __launch_bounds__(256)
void gemm2_fp16_kernel(int rowBase, int M,
                       const __half* __restrict__ Ah,
                       const float* __restrict__ B,
                       const float* __restrict__ a_src,
                       const float* __restrict__ a_dst,
                       __half* __restrict__ Ch,
                       float* __restrict__ asrc,
                       float* __restrict__ adst) {
    constexpr int BK = 32, K = HC1, N = HC2;
    constexpr int NT = 2;
    constexpr int AP = 18;

    __shared__ unsigned As2[128 * AP];
    __shared__ __half  Bs[32][40];

    const int tid = threadIdx.x;
    const int wid = tid >> 5, lane = tid & 31;
    const int gq = lane >> 2, tig = lane & 3;
    const int warp_m = wid & 3, warp_n = wid >> 2;
    const int blockRow = rowBase + blockIdx.y * 128;

    float acc[2][NT][4];
#pragma unroll
    for (int i = 0; i < 2; i++)
#pragma unroll
        for (int j = 0; j < NT; j++)
#pragma unroll
            for (int r = 0; r < 4; r++) acc[i][j][r] = 0.f;

    for (int k0 = 0; k0 < K; k0 += BK) {
        if (k0) __syncthreads();
#pragma unroll
        for (int l = 0; l < 2; l++) {
            int idx = tid + l * 256;
            int m = idx >> 2, seg = idx & 3;
            int gm = blockRow + m;
            uint4 u = make_uint4(0u, 0u, 0u, 0u);
            if (gm < M) u = *(const uint4*)&Ah[(size_t)gm * K + k0 + seg * 8];
            As2[m * AP + seg * 4 + 0] = u.x;
            As2[m * AP + seg * 4 + 1] = u.y;
            As2[m * AP + seg * 4 + 2] = u.z;
            As2[m * AP + seg * 4 + 3] = u.w;
        }
        {
            int k = tid >> 3, n4 = tid & 7;
            float4 v = *(const float4*)&B[(size_t)(k0 + k) * N + n4 * 4];
            Bs[k][n4 * 4 + 0] = __float2half_rn(v.x);
            Bs[k][n4 * 4 + 1] = __float2half_rn(v.y);
            Bs[k][n4 * 4 + 2] = __float2half_rn(v.z);
            Bs[k][n4 * 4 + 3] = __float2half_rn(v.w);
        }
        __syncthreads();

#pragma unroll
        for (int ks = 0; ks < 2; ks++) {
            const int kh2 = ks * 8;
            const int kk = ks * 16;
            unsigned a[2][4];
#pragma unroll
            for (int i = 0; i < 2; i++) {
                int m0 = warp_m * 32 + i * 16 + gq;
                a[i][0] = As2[(m0)     * AP + kh2 + tig];
                a[i][1] = As2[(m0 + 8) * AP + kh2 + tig];
                a[i][2] = As2[(m0)     * AP + kh2 + 4 + tig];
                a[i][3] = As2[(m0 + 8) * AP + kh2 + 4 + tig];
            }
#pragma unroll
            for (int j = 0; j < NT; j++) {
                int n = warp_n * 16 + j * 8 + gq;
                __half2 hb0 = __halves2half2(Bs[kk + 2 * tig][n], Bs[kk + 2 * tig + 1][n]);
                __half2 hb1 = __halves2half2(Bs[kk + 2 * tig + 8][n], Bs[kk + 2 * tig + 9][n]);
                unsigned b[2] = {*(unsigned*)&hb0, *(unsigned*)&hb1};
#pragma unroll
                for (int i = 0; i < 2; i++)
                    mma16h(acc[i][j], a[i], b);
            }
        }
    }

#pragma unroll
    for (int j = 0; j < NT; j++) {
        int head = warp_n * 4 + 2 * j + (tig >> 1);
        float2 wsrc = *(const float2*)&a_src[head * OUTC + 2 * (tig & 1)];
        float2 wdst = *(const float2*)&a_dst[head * OUTC + 2 * (tig & 1)];
        int coloff = warp_n * 16 + j * 8 + 2 * tig;
#pragma unroll
        for (int i = 0; i < 2; i++) {
#pragma unroll
            for (int rr = 0; rr < 2; rr++) {
                float p1 = acc[i][j][2 * rr] * wsrc.x + acc[i][j][2 * rr + 1] * wsrc.y;
                float p2 = acc[i][j][2 * rr] * wdst.x + acc[i][j][2 * rr + 1] * wdst.y;
                p1 += __shfl_xor_sync(0xffffffffu, p1, 1);
                p2 += __shfl_xor_sync(0xffffffffu, p2, 1);
                int row = blockRow + warp_m * 32 + i * 16 + gq + rr * 8;
                if ((tig & 1) == 0 && row < M) {
                    asrc[row * HEADS + head] = p1;
                    adst[row * HEADS + head] = p2;
                }
            }
            int row0 = blockRow + warp_m * 32 + i * 16 + gq;
            if (row0 < M)
                *(__half2*)&Ch[(size_t)row0 * N + coloff] =
                    __floats2half2_rn(acc[i][j][0], acc[i][j][1]);
            if (row0 + 8 < M)
                *(__half2*)&Ch[(size_t)(row0 + 8) * N + coloff] =
                    __floats2half2_rn(acc[i][j][2], acc[i][j][3]);
        }
    }
}

// ---------------- CSR construction ------------------------------------------
// count + per-edge rank (atomicAdd return) -> scatter becomes atomic-free.
__global__ void count_kernel(const int* __restrict__ dst) {
    int e = blockIdx.x * blockDim.x + threadIdx.x;
    if (e < EE) g_rank[e] = atomicAdd(&g_counts[dst[e]], 1);
}

__global__ void scan_blocks_kernel() {
    __shared__ int sh[SCAN_B];
    int t = threadIdx.x;
    int i = blockIdx.x * SCAN_B + t;
    int v = (i < NN) ? (g_counts[i] + 1) : 0;   // +1 self loop
    sh[t] = v;
    __syncthreads();
    for (int off = 1; off < SCAN_B; off <<= 1) {
        int x = (t >= off) ? sh[t - off] : 0;
        __syncthreads();
        sh[t] += x;
        __syncthreads();
    }
    if (i < NN) g_rowptr[i + 1] = sh[t];
    if (t == SCAN_B - 1) g_blocksums[blockIdx.x] = sh[t];
}

__global__ void scan_finalize_kernel() {
    __shared__ int s_off;
    int t = threadIdx.x;
    int sb = (blockIdx.x * 256) / SCAN_B;
    if (t < 32) {
        int v = 0;
        if (t < sb) v += g_blocksums[t];
        if (t + 32 < sb) v += g_blocksums[t + 32];
#pragma unroll
        for (int off = 16; off > 0; off >>= 1)
            v += __shfl_down_sync(0xffffffffu, v, off);
        if (t == 0) s_off = v;
    }
    __syncthreads();
    int i = blockIdx.x * 256 + t;
    if (i == 0) g_rowptr[0] = 0;
    if (i < NN) {
        int e = g_rowptr[i + 1] + s_off;
        g_rowptr[i + 1] = e;
        int begin = e - (g_counts[i] + 1);
        g_csrsrc[begin] = i;        // self loop first
    }
}

__global__ void scatter_kernel(const int* __restrict__ src,
                               const int* __restrict__ dst) {
    int e = blockIdx.x * blockDim.x + threadIdx.x;
    if (e < EE) {
        int d = dst[e];
        g_csrsrc[g_rowptr[d] + 1 + g_rank[e]] = src[e];
    }
}

// ---------------- aggregation: layer 1, warp per dst node, fp16 I/O ---------
__global__ void agg1_kernel(const __half* __restrict__ hh,
                            const float* __restrict__ asrc,
                            const float* __restrict__ adst,
                            const float* __restrict__ bias,
                            __half* __restrict__ outh,
                            int nodeBase, int nodeEnd) {
    int node = nodeBase + ((blockIdx.x * blockDim.x + threadIdx.x) >> 5);
    int lane = threadIdx.x & 31;
    if (node >= nodeEnd) return;

    int beg = g_rowptr[node];
    int end = g_rowptr[node + 1];
    int hsel = lane >> 2;

    float adst_l = adst[node * HEADS + hsel];
    float tt = asrc[node * HEADS + hsel] + adst_l;
    float aself = (tt > 0.f) ? tt : NEG * tt;   // self-loop logit = stabilizer

    float denom = 0.f;
    float acc[8];
#pragma unroll
    for (int r = 0; r < 8; r++) acc[r] = 0.f;

    int j = beg;
    for (; j + 1 < end; j += 2) {
        int s0 = g_csrsrc[j];
        int s1v = g_csrsrc[j + 1];
        float a0 = asrc[s0 * HEADS + hsel] + adst_l;
        float a1 = asrc[s1v * HEADS + hsel] + adst_l;
        uint4 u0 = *((const uint4*)(hh + (size_t)s0 * HC1) + lane);
        uint4 u1 = *((const uint4*)(hh + (size_t)s1v * HC1) + lane);
        a0 = (a0 > 0.f) ? a0 : NEG * a0;
        a1 = (a1 > 0.f) ? a1 : NEG * a1;
        float ex0 = __expf(fminf(a0 - aself, 60.f));
        float ex1 = __expf(fminf(a1 - aself, 60.f));
        denom += ex0 + ex1;
        float2 f;
        f = __half22float2(*(__half2*)&u0.x); acc[0] = fmaf(f.x, ex0, acc[0]); acc[1] = fmaf(f.y, ex0, acc[1]);
        f = __half22float2(*(__half2*)&u0.y); acc[2] = fmaf(f.x, ex0, acc[2]); acc[3] = fmaf(f.y, ex0, acc[3]);
        f = __half22float2(*(__half2*)&u0.z); acc[4] = fmaf(f.x, ex0, acc[4]); acc[5] = fmaf(f.y, ex0, acc[5]);
        f = __half22float2(*(__half2*)&u0.w); acc[6] = fmaf(f.x, ex0, acc[6]); acc[7] = fmaf(f.y, ex0, acc[7]);
        f = __half22float2(*(__half2*)&u1.x); acc[0] = fmaf(f.x, ex1, acc[0]); acc[1] = fmaf(f.y, ex1, acc[1]);
        f = __half22float2(*(__half2*)&u1.y); acc[2] = fmaf(f.x, ex1, acc[2]); acc[3] = fmaf(f.y, ex1, acc[3]);
        f = __half22float2(*(__half2*)&u1.z); acc[4] = fmaf(f.x, ex1, acc[4]); acc[5] = fmaf(f.y, ex1, acc[5]);
        f = __half22float2(*(__half2*)&u1.w); acc[6] = fmaf(f.x, ex1, acc[6]); acc[7] = fmaf(f.y, ex1, acc[7]);
    }
    if (j < end) {
        int s = g_csrsrc[j];
        float a = asrc[s * HEADS + hsel] + adst_l;
        a = (a > 0.f) ? a : NEG * a;
        float ex = __expf(fminf(a - aself, 60.f));
        denom += ex;
        uint4 u = *((const uint4*)(hh + (size_t)s * HC1) + lane);
        float2 f;
        f = __half22float2(*(__half2*)&u.x); acc[0] = fmaf(f.x, ex, acc[0]); acc[1] = fmaf(f.y, ex, acc[1]);
        f = __half22float2(*(__half2*)&u.y); acc[2] = fmaf(f.x, ex, acc[2]); acc[3] = fmaf(f.y, ex, acc[3]);
        f = __half22float2(*(__half2*)&u.z); acc[4] = fmaf(f.x, ex, acc[4]); acc[5] = fmaf(f.y, ex, acc[5]);
        f = __half22float2(*(__half2*)&u.w); acc[6] = fmaf(f.x, ex, acc[6]); acc[7] = fmaf(f.y, ex, acc[7]);
    }

    float d = denom + 1e-16f;
    const float4* b4 = (const float4*)bias + lane * 2;
    float4 bb0 = b4[0], bb1 = b4[1];
    float o[8];
    o[0] = acc[0] / d + bb0.x; o[1] = acc[1] / d + bb0.y;
    o[2] = acc[2] / d + bb0.z; o[3] = acc[3] / d + bb0.w;
    o[4] = acc[4] / d + bb1.x; o[5] = acc[5] / d + bb1.y;
    o[6] = acc[6] / d + bb1.z; o[7] = acc[7] / d + bb1.w;
#pragma unroll
    for (int r = 0; r < 8; r++) o[r] = (o[r] > 0.f) ? o[r] : NEG * o[r];

    __half2 ho[4];
    ho[0] = __floats2half2_rn(o[0], o[1]);
    ho[1] = __floats2half2_rn(o[2], o[3]);
    ho[2] = __floats2half2_rn(o[4], o[5]);
    ho[3] = __floats2half2_rn(o[6], o[7]);
    *(uint4*)(outh + (size_t)node * HC1 + lane * 8) = *(uint4*)ho;
}

// ---------------- aggregation: layer 2 (C=4), fp16 gather, unroll 4 ---------
__global__ void agg2_kernel(const __half* __restrict__ hh,
                            const float* __restrict__ asrc,
                            const float* __restrict__ adst,
                            const float* __restrict__ bias,
                            float* __restrict__ out) {
    int warp = (blockIdx.x * blockDim.x + threadIdx.x) >> 5;
    int lane = threadIdx.x & 31;
    if (warp >= NN) return;

    int beg = g_rowptr[warp];
    int end = g_rowptr[warp + 1];
    int hd = lane >> 2;

    float adst_l = adst[warp * HEADS + hd];
    float tt = asrc[warp * HEADS + hd] + adst_l;
    float aself = (tt > 0.f) ? tt : NEG * tt;

    float denom = 0.f;
    float acc = 0.f;
    int j = beg;
    for (; j + 3 < end; j += 4) {
        int s0 = g_csrsrc[j], s1 = g_csrsrc[j + 1];
        int s2v = g_csrsrc[j + 2], s3 = g_csrsrc[j + 3];
        float a0 = asrc[s0 * HEADS + hd] + adst_l;
        float a1 = asrc[s1 * HEADS + hd] + adst_l;
        float a2 = asrc[s2v * HEADS + hd] + adst_l;
        float a3 = asrc[s3 * HEADS + hd] + adst_l;
        float v0 = __half2float(hh[(size_t)s0 * HC2 + lane]);
        float v1 = __half2float(hh[(size_t)s1 * HC2 + lane]);
        float v2 = __half2float(hh[(size_t)s2v * HC2 + lane]);
        float v3 = __half2float(hh[(size_t)s3 * HC2 + lane]);
        a0 = (a0 > 0.f) ? a0 : NEG * a0;
        a1 = (a1 > 0.f) ? a1 : NEG * a1;
        a2 = (a2 > 0.f) ? a2 : NEG * a2;
        a3 = (a3 > 0.f) ? a3 : NEG * a3;
        float ex0 = __expf(fminf(a0 - aself, 60.f));
        float ex1 = __expf(fminf(a1 - aself, 60.f));
        float ex2 = __expf(fminf(a2 - aself, 60.f));
        float ex3 = __expf(fminf(a3 - aself, 60.f));
        denom += (ex0 + ex1) + (ex2 + ex3);
        acc = fmaf(v0, ex0, acc);
        acc = fmaf(v1, ex1, acc);
        acc = fmaf(v2, ex2, acc);
        acc = fmaf(v3, ex3, acc);
    }
    for (; j < end; j++) {
        int s = g_csrsrc[j];
        float a = asrc[s * HEADS + hd] + adst_l;
        a = (a > 0.f) ? a : NEG * a;
        float ex = __expf(fminf(a - aself, 60.f));
        denom += ex;
        acc = fmaf(__half2float(hh[(size_t)s * HC2 + lane]), ex, acc);
    }

    out[(size_t)warp * HC2 + lane] = acc / (denom + 1e-16f) + bias[lane];
}

// ---------------- launch ------------------------------------------------------
extern "C" void kernel_launch(void* const* d_in, const int* in_sizes, int n_in,
                              void* d_out, int out_size) {
    const float* x      = (const float*)d_in[0];
    const int*   ei     = (const int*)d_in[1];
    const float* W1     = (const float*)d_in[2];
    const float* a_src1 = (const float*)d_in[3];
    const float* a_dst1 = (const float*)d_in[4];
    const float* b1     = (const float*)d_in[5];
    const float* W2     = (const float*)d_in[6];
    const float* a_src2 = (const float*)d_in[7];
    const float* a_dst2 = (const float*)d_in[8];
    const float* b2     = (const float*)d_in[9];
    float* out = (float*)d_out;

    const int* src = ei;
    const int* dst = ei + EE;

    float *as1, *ad1, *as2, *ad2;
    __half *h1h, *o1h, *h2h;
    int *cnts;
    cudaGetSymbolAddress((void**)&h1h, g_h1h);
    cudaGetSymbolAddress((void**)&o1h, g_o1h);
    cudaGetSymbolAddress((void**)&h2h, g_h2h);
    cudaGetSymbolAddress((void**)&as1, g_asrc1);
    cudaGetSymbolAddress((void**)&ad1, g_adst1);
    cudaGetSymbolAddress((void**)&as2, g_asrc2);
    cudaGetSymbolAddress((void**)&ad2, g_adst2);
    cudaGetSymbolAddress((void**)&cnts, g_counts);

    static cudaStream_t s2 = nullptr;
    static cudaEvent_t evFork = nullptr, evJoin = nullptr, evA = nullptr, evB = nullptr;
    if (s2 == nullptr) {
        cudaStreamCreateWithFlags(&s2, cudaStreamNonBlocking);
        cudaEventCreateWithFlags(&evFork, cudaEventDisableTiming);
        cudaEventCreateWithFlags(&evJoin, cudaEventDisableTiming);
        cudaEventCreateWithFlags(&evA, cudaEventDisableTiming);
        cudaEventCreateWithFlags(&evB, cudaEventDisableTiming);
    }

    // --- fork: CSR build on s2, GEMM1 on main stream -------------------------
    cudaEventRecord(evFork, 0);
    cudaStreamWaitEvent(s2, evFork, 0);

    cudaMemsetAsync(cnts, 0, NN * sizeof(int), s2);
    count_kernel<<<(EE + 255) / 256, 256, 0, s2>>>(dst);
    scan_blocks_kernel<<<NBLK, SCAN_B, 0, s2>>>();
    scan_finalize_kernel<<<(NN + 255) / 256, 256, 0, s2>>>();
    scatter_kernel<<<(EE + 255) / 256, 256, 0, s2>>>(src, dst);
    cudaEventRecord(evJoin, s2);

    // main stream: GEMM1 (fp16-split mma, fused alphas + fp16 out)
    {
        dim3 grid(2, (NN + 127) / 128);
        gemm1_fused_kernel<<<grid, 256>>>(NN, x, W1, a_src1, a_dst1,
                                          h1h, as1, ad1);
    }

    // --- join, then half-split agg1 / gemm2 pipeline --------------------------
    cudaStreamWaitEvent(0, evJoin, 0);
    agg1_kernel<<<(NH0 * 32 + 255) / 256, 256>>>(h1h, as1, ad1, b1, o1h, 0, NH0);
    cudaEventRecord(evA, 0);
    agg1_kernel<<<((NN - NH0) * 32 + 255) / 256, 256>>>(h1h, as1, ad1, b1, o1h, NH0, NN);

    // side stream: gemm2 on first half (overlaps agg1 second half)
    cudaStreamWaitEvent(s2, evA, 0);
    {
        dim3 grid(1, NH0 / 128);
        gemm2_fp16_kernel<<<grid, 256, 0, s2>>>(0, NN, o1h, W2, a_src2, a_dst2,
                                                h2h, as2, ad2);
    }
    cudaEventRecord(evB, s2);

    // main stream: gemm2 on second half
    {
        dim3 grid(1, (NN - NH0 + 127) / 128);
        gemm2_fp16_kernel<<<grid, 256>>>(NH0, NN, o1h, W2, a_src2, a_dst2,
                                         h2h, as2, ad2);
    }

    // --- join both gemm2 halves, then agg2 -----------------------------------
    cudaStreamWaitEvent(0, evB, 0);
    agg2_kernel<<<(NN * 32 + 255) / 256, 256>>>(h2h, as2, ad2, b2, out);
}